// round 2
// baseline (speedup 1.0000x reference)
#include <cuda_runtime.h>

#define Bsz 2048
#define Lsz 512
#define Esz 64
#define Hsz 128
#define Dsz 256
#define Vsz 1000

// Scratch (static device globals: no allocation, graph-safe)
__device__ float g_wkT[Dsz * Hsz];            // Wk transposed: [d][h]
__device__ float g_qproj[Bsz * Hsz];          // query @ Wq^T
__device__ float g_ctx[Bsz * Dsz];            // attention context
__device__ float g_x0[Bsz * (Esz + Dsz)];     // [embed | context]
__device__ float g_gi[Bsz * 3 * Hsz];         // GRU input gates
__device__ float g_gh[Bsz * 3 * Hsz];         // GRU hidden gates

// ---------------------------------------------------------------------------
// Transpose Wk (128x256 -> 256x128) so the scores GEMM B-loads are coalesced.
// ---------------------------------------------------------------------------
__global__ void transpose_wk_kernel(const float* __restrict__ wk) {
    int i = blockIdx.x * blockDim.x + threadIdx.x;
    if (i < Hsz * Dsz) {
        int h = i / Dsz, d = i % Dsz;
        g_wkT[d * Hsz + h] = wk[i];
    }
}

// ---------------------------------------------------------------------------
// Generic tiled GEMM: C[m,n] = sum_k A[m,k] * W[n,k] (+ bias[n])
// M = 2048 (by grid.y), tile 64x64, K multiple of 16, N arbitrary.
// ---------------------------------------------------------------------------
__global__ __launch_bounds__(256) void gemm_bias_kernel(
    const float* __restrict__ A, const float* __restrict__ W,
    const float* __restrict__ bias, float* __restrict__ C, int N, int K)
{
    __shared__ float As[16][64];
    __shared__ float Ws[16][64];
    int t  = threadIdx.x;
    int m0 = blockIdx.y * 64;
    int n0 = blockIdx.x * 64;
    int tx = t & 15, ty = t >> 4;
    int lm = t >> 2, kv = t & 3;

    float acc[4][4] = {};
    for (int k0 = 0; k0 < K; k0 += 16) {
        float4 avv = *(const float4*)(A + (size_t)(m0 + lm) * K + k0 + kv * 4);
        As[kv*4+0][lm] = avv.x; As[kv*4+1][lm] = avv.y;
        As[kv*4+2][lm] = avv.z; As[kv*4+3][lm] = avv.w;
        float4 wv = make_float4(0.f, 0.f, 0.f, 0.f);
        if (n0 + lm < N)
            wv = *(const float4*)(W + (size_t)(n0 + lm) * K + k0 + kv * 4);
        Ws[kv*4+0][lm] = wv.x; Ws[kv*4+1][lm] = wv.y;
        Ws[kv*4+2][lm] = wv.z; Ws[kv*4+3][lm] = wv.w;
        __syncthreads();
        #pragma unroll
        for (int kk = 0; kk < 16; kk++) {
            float a[4], b[4];
            #pragma unroll
            for (int j = 0; j < 4; j++) a[j] = As[kk][ty * 4 + j];
            float4 bv = *(const float4*)&Ws[kk][tx * 4];
            b[0] = bv.x; b[1] = bv.y; b[2] = bv.z; b[3] = bv.w;
            #pragma unroll
            for (int j = 0; j < 4; j++)
                #pragma unroll
                for (int i = 0; i < 4; i++)
                    acc[j][i] += a[j] * b[i];
        }
        __syncthreads();
    }
    #pragma unroll
    for (int j = 0; j < 4; j++) {
        int m = m0 + ty * 4 + j;
        #pragma unroll
        for (int i = 0; i < 4; i++) {
            int n = n0 + tx * 4 + i;
            if (n < N) {
                float v = acc[j][i];
                if (bias) v += bias[n];
                C[(size_t)m * N + n] = v;
            }
        }
    }
}

// ---------------------------------------------------------------------------
// Scores: per (b, 64-l tile): proj = enc[b,l,:] @ Wk^T  (64x128, K=256),
// fused epilogue: score[l] = sum_h v[h] * tanh(proj + qproj[b,h]).
// Raw scores written directly to the attn_weights output region.
// ---------------------------------------------------------------------------
__global__ __launch_bounds__(256) void scores_kernel(
    const float* __restrict__ enc, const float* __restrict__ attn_v,
    float* __restrict__ scores_out)
{
    __shared__ float As[16][64];    // [k][l]
    __shared__ float Bs[16][128];   // [k][h]
    __shared__ float qs[128], vs[128];
    int t    = threadIdx.x;
    int b    = blockIdx.y;
    int l0   = blockIdx.x * 64;
    int lane = t & 31, warp = t >> 5;
    int lr   = t >> 2,  dv   = t & 3;

    if (t < 128) { qs[t] = g_qproj[b * Hsz + t]; vs[t] = attn_v[t]; }

    float acc[8][4] = {};
    const float* encb = enc + (size_t)b * Lsz * Dsz;

    for (int k0 = 0; k0 < Dsz; k0 += 16) {
        float4 avv = *(const float4*)(encb + (size_t)(l0 + lr) * Dsz + k0 + dv * 4);
        As[dv*4+0][lr] = avv.x; As[dv*4+1][lr] = avv.y;
        As[dv*4+2][lr] = avv.z; As[dv*4+3][lr] = avv.w;
        #pragma unroll
        for (int i = 0; i < 2; i++) {
            int s  = t + i * 256;
            int dd = s >> 5, hv = s & 31;
            *(float4*)&Bs[dd][hv * 4] =
                *(const float4*)(g_wkT + (size_t)(k0 + dd) * Hsz + hv * 4);
        }
        __syncthreads();
        #pragma unroll
        for (int kk = 0; kk < 16; kk++) {
            float a[8];
            #pragma unroll
            for (int r = 0; r < 8; r++) a[r] = As[kk][warp * 8 + r];
            float4 bv = *(const float4*)&Bs[kk][lane * 4];
            #pragma unroll
            for (int r = 0; r < 8; r++) {
                acc[r][0] += a[r] * bv.x; acc[r][1] += a[r] * bv.y;
                acc[r][2] += a[r] * bv.z; acc[r][3] += a[r] * bv.w;
            }
        }
        __syncthreads();
    }

    #pragma unroll
    for (int r = 0; r < 8; r++) {
        float s = 0.f;
        #pragma unroll
        for (int c = 0; c < 4; c++) {
            int h = lane * 4 + c;
            s += vs[h] * tanhf(acc[r][c] + qs[h]);
        }
        #pragma unroll
        for (int off = 16; off > 0; off >>= 1)
            s += __shfl_xor_sync(0xffffffffu, s, off);
        if (lane == 0)
            scores_out[(size_t)b * Lsz + l0 + warp * 8 + r] = s;
    }
}

// ---------------------------------------------------------------------------
// In-place softmax over L=512 per batch row (256 threads, 2 elems each).
// ---------------------------------------------------------------------------
__global__ void softmax_kernel(float* __restrict__ w) {
    __shared__ float red[256];
    int b = blockIdx.x, t = threadIdx.x;
    float* wb = w + (size_t)b * Lsz;
    float v0 = wb[t], v1 = wb[t + 256];
    red[t] = fmaxf(v0, v1);
    __syncthreads();
    for (int s = 128; s > 0; s >>= 1) {
        if (t < s) red[t] = fmaxf(red[t], red[t + s]);
        __syncthreads();
    }
    float mx = red[0];
    __syncthreads();
    float e0 = __expf(v0 - mx), e1 = __expf(v1 - mx);
    red[t] = e0 + e1;
    __syncthreads();
    for (int s = 128; s > 0; s >>= 1) {
        if (t < s) red[t] += red[t + s];
        __syncthreads();
    }
    float inv = 1.f / red[0];
    wb[t] = e0 * inv;
    wb[t + 256] = e1 * inv;
}

// ---------------------------------------------------------------------------
// context[b,d] = sum_l w[b,l] * enc[b,l,d]   (coalesced over d)
// ---------------------------------------------------------------------------
__global__ __launch_bounds__(256) void context_kernel(
    const float* __restrict__ enc, const float* __restrict__ w)
{
    __shared__ float ws[Lsz];
    int b = blockIdx.x, t = threadIdx.x;
    ws[t]       = w[(size_t)b * Lsz + t];
    ws[t + 256] = w[(size_t)b * Lsz + t + 256];
    __syncthreads();
    const float* e = enc + (size_t)b * Lsz * Dsz + t;
    float acc = 0.f;
    #pragma unroll 8
    for (int l = 0; l < Lsz; l++) acc += ws[l] * e[(size_t)l * Dsz];
    g_ctx[b * Dsz + t] = acc;
}

// ---------------------------------------------------------------------------
// x0 = concat(embed, context)
// ---------------------------------------------------------------------------
__global__ void concat_kernel(const float* __restrict__ embed) {
    int i = blockIdx.x * blockDim.x + threadIdx.x;
    if (i >= Bsz * (Esz + Dsz)) return;
    int b = i / (Esz + Dsz), c = i - b * (Esz + Dsz);
    g_x0[i] = (c < Esz) ? embed[b * Esz + c] : g_ctx[b * Dsz + (c - Esz)];
}

// ---------------------------------------------------------------------------
// GRU gate combine: h_new from g_gi, g_gh, h_prev.
// ---------------------------------------------------------------------------
__global__ void gru_kernel(const float* __restrict__ hprev, float* __restrict__ hnew) {
    int b = blockIdx.x, h = threadIdx.x;
    int base = b * 3 * Hsz;
    float r = 1.f / (1.f + __expf(-(g_gi[base + h]          + g_gh[base + h])));
    float z = 1.f / (1.f + __expf(-(g_gi[base + Hsz + h]    + g_gh[base + Hsz + h])));
    float n = tanhf(g_gi[base + 2 * Hsz + h] + r * g_gh[base + 2 * Hsz + h]);
    hnew[b * Hsz + h] = (1.f - z) * n + z * hprev[b * Hsz + h];
}

// ---------------------------------------------------------------------------
extern "C" void kernel_launch(void* const* d_in, const int* in_sizes, int n_in,
                              void* d_out, int out_size)
{
    const float* embed  = (const float*)d_in[0];
    const float* hidden = (const float*)d_in[1];   // (2, B, H)
    const float* enc    = (const float*)d_in[2];   // (B, L, D)
    const float* Wq     = (const float*)d_in[3];
    const float* Wk     = (const float*)d_in[4];
    const float* av     = (const float*)d_in[5];
    const float* Wih0   = (const float*)d_in[6];
    const float* Whh0   = (const float*)d_in[7];
    const float* bih0   = (const float*)d_in[8];
    const float* bhh0   = (const float*)d_in[9];
    const float* Wih1   = (const float*)d_in[10];
    const float* Whh1   = (const float*)d_in[11];
    const float* bih1   = (const float*)d_in[12];
    const float* bhh1   = (const float*)d_in[13];
    const float* Wout   = (const float*)d_in[14];
    const float* bout   = (const float*)d_in[15];

    float* out_logits = (float*)d_out;                            // B*V
    float* out_hidden = out_logits + (size_t)Bsz * Vsz;           // 2*B*H
    float* out_attnw  = out_hidden + (size_t)2 * Bsz * Hsz;       // B*L

    float *p_qproj, *p_x0, *p_gi, *p_gh;
    cudaGetSymbolAddress((void**)&p_qproj, g_qproj);
    cudaGetSymbolAddress((void**)&p_x0,    g_x0);
    cudaGetSymbolAddress((void**)&p_gi,    g_gi);
    cudaGetSymbolAddress((void**)&p_gh,    g_gh);

    const float* h0_prev = hidden;                       // layer 0 state
    const float* h1_prev = hidden + (size_t)Bsz * Hsz;   // layer 1 state (= query)

    // 1) Wk transpose + query projection
    transpose_wk_kernel<<<(Hsz * Dsz + 255) / 256, 256>>>(Wk);
    gemm_bias_kernel<<<dim3(Hsz / 64, Bsz / 64), 256>>>(
        h1_prev, Wq, nullptr, p_qproj, Hsz, Hsz);

    // 2) attention scores (fused tanh + v-dot), softmax, context
    scores_kernel<<<dim3(Lsz / 64, Bsz), 256>>>(enc, av, out_attnw);
    softmax_kernel<<<Bsz, 256>>>(out_attnw);
    context_kernel<<<Bsz, 256>>>(enc, out_attnw);

    // 3) GRU layer 0
    concat_kernel<<<(Bsz * (Esz + Dsz) + 255) / 256, 256>>>(embed);
    gemm_bias_kernel<<<dim3(384 / 64, Bsz / 64), 256>>>(
        p_x0, Wih0, bih0, p_gi, 3 * Hsz, Esz + Dsz);
    gemm_bias_kernel<<<dim3(384 / 64, Bsz / 64), 256>>>(
        h0_prev, Whh0, bhh0, p_gh, 3 * Hsz, Hsz);
    gru_kernel<<<Bsz, Hsz>>>(h0_prev, out_hidden);

    // 4) GRU layer 1
    gemm_bias_kernel<<<dim3(384 / 64, Bsz / 64), 256>>>(
        out_hidden, Wih1, bih1, p_gi, 3 * Hsz, Hsz);
    gemm_bias_kernel<<<dim3(384 / 64, Bsz / 64), 256>>>(
        h1_prev, Whh1, bhh1, p_gh, 3 * Hsz, Hsz);
    gru_kernel<<<Bsz, Hsz>>>(h1_prev, out_hidden + (size_t)Bsz * Hsz);

    // 5) output projection
    gemm_bias_kernel<<<dim3((Vsz + 63) / 64, Bsz / 64), 256>>>(
        out_hidden + (size_t)Bsz * Hsz, Wout, bout, out_logits, Vsz, Hsz);
}

// round 4
// speedup vs baseline: 1.5664x; 1.5664x over previous
#include <cuda_runtime.h>
#include <cuda_bf16.h>
#include <cstdint>

#define Bsz 2048
#define Lsz 512
#define Esz 64
#define Hsz 128
#define Dsz 256
#define Vsz 1000

#define SMEM_SWIZZLE_128B(off) ((off) ^ (((off) >> 3) & 0x70))

__device__ __forceinline__ uint32_t smem_to_u32(const void* p) {
    uint32_t a;
    asm("{ .reg .u64 t; cvta.to.shared.u64 t, %1; cvt.u32.u64 %0, t; }"
        : "=r"(a) : "l"(p));
    return a;
}

// ldmatrix x4 (sm_75+, no arch-accel gating)
__device__ __forceinline__ void ldmat4(uint32_t* r, uint32_t addr) {
    asm volatile("ldmatrix.sync.aligned.m8n8.x4.shared.b16 {%0,%1,%2,%3}, [%4];"
                 : "=r"(r[0]), "=r"(r[1]), "=r"(r[2]), "=r"(r[3]) : "r"(addr));
}

// mma m16n8k16 row.col f32 <- bf16 x bf16 (sm_80+)
__device__ __forceinline__ void mma16816(float* d, const uint32_t* a, uint32_t b0, uint32_t b1) {
    asm volatile("mma.sync.aligned.m16n8k16.row.col.f32.bf16.bf16.f32 "
                 "{%0,%1,%2,%3}, {%4,%5,%6,%7}, {%8,%9}, {%0,%1,%2,%3};"
                 : "+f"(d[0]), "+f"(d[1]), "+f"(d[2]), "+f"(d[3])
                 : "r"(a[0]), "r"(a[1]), "r"(a[2]), "r"(a[3]), "r"(b0), "r"(b1));
}

// accurate fast tanh: 2 MUFU (ex2 + rcp.approx via fdividef)
__device__ __forceinline__ float tanh_acc(float x) {
    float ax = fabsf(x);
    float t  = __expf(-2.f * ax);
    float r  = __fdividef(1.f - t, 1.f + t);
    return copysignf(r, x);
}

// ===========================================================================
// Scratch
// ===========================================================================
__device__ float g_qproj[Bsz * Hsz];
__device__ float g_ctx[Bsz * Dsz];
__device__ float g_x0[Bsz * (Esz + Dsz)];
__device__ float g_gi[Bsz * 3 * Hsz];
__device__ float g_gh[Bsz * 3 * Hsz];
__device__ __nv_bfloat16 g_wkHi[Hsz * Dsz];   // [h][d] bf16 hi
__device__ __nv_bfloat16 g_wkLo[Hsz * Dsz];   // [h][d] bf16 residual

// ---------------------------------------------------------------------------
__global__ void wk_split_kernel(const float* __restrict__ wk) {
    int i = blockIdx.x * blockDim.x + threadIdx.x;
    if (i < Hsz * Dsz) {
        float w = wk[i];
        __nv_bfloat16 hi = __float2bfloat16(w);
        g_wkHi[i] = hi;
        g_wkLo[i] = __float2bfloat16(w - __bfloat162float(hi));
    }
}

// ---------------------------------------------------------------------------
// Generic tiled fp32 GEMM: C[m,n] = sum_k A[m,k] * W[n,k] (+ bias[n])
// ---------------------------------------------------------------------------
__global__ __launch_bounds__(256) void gemm_bias_kernel(
    const float* __restrict__ A, const float* __restrict__ W,
    const float* __restrict__ bias, float* __restrict__ C, int N, int K)
{
    __shared__ float As[16][64];
    __shared__ float Ws[16][64];
    int t  = threadIdx.x;
    int m0 = blockIdx.y * 64;
    int n0 = blockIdx.x * 64;
    int tx = t & 15, ty = t >> 4;
    int lm = t >> 2, kv = t & 3;

    float acc[4][4] = {};
    for (int k0 = 0; k0 < K; k0 += 16) {
        float4 avv = *(const float4*)(A + (size_t)(m0 + lm) * K + k0 + kv * 4);
        As[kv*4+0][lm] = avv.x; As[kv*4+1][lm] = avv.y;
        As[kv*4+2][lm] = avv.z; As[kv*4+3][lm] = avv.w;
        float4 wv = make_float4(0.f, 0.f, 0.f, 0.f);
        if (n0 + lm < N)
            wv = *(const float4*)(W + (size_t)(n0 + lm) * K + k0 + kv * 4);
        Ws[kv*4+0][lm] = wv.x; Ws[kv*4+1][lm] = wv.y;
        Ws[kv*4+2][lm] = wv.z; Ws[kv*4+3][lm] = wv.w;
        __syncthreads();
        #pragma unroll
        for (int kk = 0; kk < 16; kk++) {
            float a[4];
            #pragma unroll
            for (int j = 0; j < 4; j++) a[j] = As[kk][ty * 4 + j];
            float4 bv = *(const float4*)&Ws[kk][tx * 4];
            #pragma unroll
            for (int j = 0; j < 4; j++) {
                acc[j][0] += a[j] * bv.x; acc[j][1] += a[j] * bv.y;
                acc[j][2] += a[j] * bv.z; acc[j][3] += a[j] * bv.w;
            }
        }
        __syncthreads();
    }
    #pragma unroll
    for (int j = 0; j < 4; j++) {
        int m = m0 + ty * 4 + j;
        #pragma unroll
        for (int i = 0; i < 4; i++) {
            int n = n0 + tx * 4 + i;
            if (n < N) {
                float v = acc[j][i];
                if (bias) v += bias[n];
                C[(size_t)m * N + n] = v;
            }
        }
    }
}

// ===========================================================================
// Scores via mma.sync bf16 3-term split.
// Block: 128 l-rows x 128 h-cols, K=256 in 4 chunks of 64.
// 8 warps as 4(row) x 2(col): warp tile 32 l x 64 h.
// Epilogue: score[l] = sum_h v[h] * tanh(D[l,h] + qproj[b,h]).
// ===========================================================================
#define SA_HI 0
#define SA_LO 16384
#define SB_HI 32768
#define SB_LO 49152
#define SC_SMEM 65536

__global__ __launch_bounds__(256, 1) void scores_mma_kernel(
    const float* __restrict__ enc, const float* __restrict__ attn_v,
    float* __restrict__ scores_out)
{
    extern __shared__ char smem[];
    __shared__ float qs[128], vs[128], sred[2][128];
    uint32_t sbase = smem_to_u32(smem);

    int t    = threadIdx.x;
    int lane = t & 31, w = t >> 5;
    int wr   = w & 3,  wc = w >> 2;
    int b    = blockIdx.y;
    int l0   = blockIdx.x * 128;

    if (t < 128) { qs[t] = g_qproj[b * Hsz + t]; vs[t] = attn_v[t]; }

    const float* encb = enc + (size_t)b * Lsz * Dsz + (size_t)l0 * Dsz;

    float acc[2][8][4];
    #pragma unroll
    for (int mt = 0; mt < 2; mt++)
        #pragma unroll
        for (int nt = 0; nt < 8; nt++)
            #pragma unroll
            for (int i = 0; i < 4; i++) acc[mt][nt][i] = 0.f;

    for (int c = 0; c < 4; c++) {
        int d0 = c * 64;
        // ---- stage A: enc[l0..l0+128][d0..d0+64] -> bf16 hi/lo, swizzled ----
        #pragma unroll
        for (int i = 0; i < 8; i++) {
            int idx = t + i * 256;          // float4 units, 16 per row
            int row = idx >> 4;
            int dq  = idx & 15;
            float4 v4 = *(const float4*)(encb + (size_t)row * Dsz + d0 + dq * 4);
            __nv_bfloat16 h0 = __float2bfloat16(v4.x);
            __nv_bfloat16 h1 = __float2bfloat16(v4.y);
            __nv_bfloat16 h2 = __float2bfloat16(v4.z);
            __nv_bfloat16 h3 = __float2bfloat16(v4.w);
            __nv_bfloat16 r0 = __float2bfloat16(v4.x - __bfloat162float(h0));
            __nv_bfloat16 r1 = __float2bfloat16(v4.y - __bfloat162float(h1));
            __nv_bfloat16 r2 = __float2bfloat16(v4.z - __bfloat162float(h2));
            __nv_bfloat16 r3 = __float2bfloat16(v4.w - __bfloat162float(h3));
            uint32_t off = SMEM_SWIZZLE_128B((uint32_t)(row * 128 + dq * 8));
            uint2 hv, lv;
            hv.x = (uint32_t)__bfloat16_as_ushort(h0) | ((uint32_t)__bfloat16_as_ushort(h1) << 16);
            hv.y = (uint32_t)__bfloat16_as_ushort(h2) | ((uint32_t)__bfloat16_as_ushort(h3) << 16);
            lv.x = (uint32_t)__bfloat16_as_ushort(r0) | ((uint32_t)__bfloat16_as_ushort(r1) << 16);
            lv.y = (uint32_t)__bfloat16_as_ushort(r2) | ((uint32_t)__bfloat16_as_ushort(r3) << 16);
            *(uint2*)(smem + SA_HI + off) = hv;
            *(uint2*)(smem + SA_LO + off) = lv;
        }
        // ---- stage B: Wk hi/lo [h][d0..d0+64], swizzled ----
        #pragma unroll
        for (int i = 0; i < 4; i++) {
            int idx = t + i * 256;          // 16B units, 8 per row
            int row = idx >> 3;
            int u   = idx & 7;
            uint32_t off = SMEM_SWIZZLE_128B((uint32_t)(row * 128 + u * 16));
            *(uint4*)(smem + SB_HI + off) = *(const uint4*)(g_wkHi + (size_t)row * Dsz + d0 + u * 8);
            *(uint4*)(smem + SB_LO + off) = *(const uint4*)(g_wkLo + (size_t)row * Dsz + d0 + u * 8);
        }
        __syncthreads();

        // ---- 4 k-steps of 16 within the chunk ----
        #pragma unroll
        for (int ks = 0; ks < 4; ks++) {
            int kb = ks * 32;               // byte offset within 128B row
            uint32_t ah[2][4], al[2][4];
            #pragma unroll
            for (int mt = 0; mt < 2; mt++) {
                int row  = wr * 32 + mt * 16 + (lane & 15);
                int colb = kb + (lane >> 4) * 16;
                uint32_t off = SMEM_SWIZZLE_128B((uint32_t)(row * 128 + colb));
                ldmat4(ah[mt], sbase + SA_HI + off);
                ldmat4(al[mt], sbase + SA_LO + off);
            }
            uint32_t bh[8][2], bl[8][2];
            #pragma unroll
            for (int p = 0; p < 4; p++) {
                int row  = wc * 64 + p * 16 + (lane & 15);
                int colb = kb + (lane >> 4) * 16;
                uint32_t off = SMEM_SWIZZLE_128B((uint32_t)(row * 128 + colb));
                uint32_t r4[4];
                ldmat4(r4, sbase + SB_HI + off);
                bh[p*2][0] = r4[0]; bh[p*2+1][0] = r4[1];
                bh[p*2][1] = r4[2]; bh[p*2+1][1] = r4[3];
                ldmat4(r4, sbase + SB_LO + off);
                bl[p*2][0] = r4[0]; bl[p*2+1][0] = r4[1];
                bl[p*2][1] = r4[2]; bl[p*2+1][1] = r4[3];
            }
            #pragma unroll
            for (int mt = 0; mt < 2; mt++)
                #pragma unroll
                for (int nt = 0; nt < 8; nt++) {
                    mma16816(acc[mt][nt], ah[mt], bh[nt][0], bh[nt][1]);
                    mma16816(acc[mt][nt], al[mt], bh[nt][0], bh[nt][1]);
                    mma16816(acc[mt][nt], ah[mt], bl[nt][0], bl[nt][1]);
                }
        }
        __syncthreads();
    }

    // ---- epilogue ----
    // acc element (mt,nt,i): row = wr*32 + mt*16 + (lane>>2) + (i>=2 ? 8:0)
    //                        col = wc*64 + nt*8 + (lane&3)*2 + (i&1)
    float part[4];
    #pragma unroll
    for (int mt = 0; mt < 2; mt++)
        #pragma unroll
        for (int half = 0; half < 2; half++) {
            float p = 0.f;
            #pragma unroll
            for (int nt = 0; nt < 8; nt++)
                #pragma unroll
                for (int j = 0; j < 2; j++) {
                    int h = wc * 64 + nt * 8 + (lane & 3) * 2 + j;
                    float e = acc[mt][nt][half * 2 + j] + qs[h];
                    p += vs[h] * tanh_acc(e);
                }
            part[mt * 2 + half] = p;
        }
    #pragma unroll
    for (int k = 0; k < 4; k++) {
        part[k] += __shfl_xor_sync(0xffffffffu, part[k], 1);
        part[k] += __shfl_xor_sync(0xffffffffu, part[k], 2);
    }
    if ((lane & 3) == 0) {
        #pragma unroll
        for (int mt = 0; mt < 2; mt++)
            #pragma unroll
            for (int half = 0; half < 2; half++) {
                int row = wr * 32 + mt * 16 + half * 8 + (lane >> 2);
                sred[wc][row] = part[mt * 2 + half];
            }
    }
    __syncthreads();
    if (t < 128)
        scores_out[(size_t)b * Lsz + l0 + t] = sred[0][t] + sred[1][t];
}

// ---------------------------------------------------------------------------
__global__ void softmax_kernel(float* __restrict__ w) {
    __shared__ float red[256];
    int b = blockIdx.x, t = threadIdx.x;
    float* wb = w + (size_t)b * Lsz;
    float v0 = wb[t], v1 = wb[t + 256];
    red[t] = fmaxf(v0, v1);
    __syncthreads();
    for (int s = 128; s > 0; s >>= 1) {
        if (t < s) red[t] = fmaxf(red[t], red[t + s]);
        __syncthreads();
    }
    float mx = red[0];
    __syncthreads();
    float e0 = __expf(v0 - mx), e1 = __expf(v1 - mx);
    red[t] = e0 + e1;
    __syncthreads();
    for (int s = 128; s > 0; s >>= 1) {
        if (t < s) red[t] += red[t + s];
        __syncthreads();
    }
    float inv = 1.f / red[0];
    wb[t] = e0 * inv;
    wb[t + 256] = e1 * inv;
}

// ---------------------------------------------------------------------------
__global__ __launch_bounds__(256) void context_kernel(
    const float* __restrict__ enc, const float* __restrict__ w)
{
    __shared__ float ws[Lsz];
    int b = blockIdx.x, t = threadIdx.x;
    ws[t]       = w[(size_t)b * Lsz + t];
    ws[t + 256] = w[(size_t)b * Lsz + t + 256];
    __syncthreads();
    const float* e = enc + (size_t)b * Lsz * Dsz + t;
    float acc = 0.f;
    #pragma unroll 8
    for (int l = 0; l < Lsz; l++) acc += ws[l] * e[(size_t)l * Dsz];
    g_ctx[b * Dsz + t] = acc;
}

__global__ void concat_kernel(const float* __restrict__ embed) {
    int i = blockIdx.x * blockDim.x + threadIdx.x;
    if (i >= Bsz * (Esz + Dsz)) return;
    int b = i / (Esz + Dsz), c = i - b * (Esz + Dsz);
    g_x0[i] = (c < Esz) ? embed[b * Esz + c] : g_ctx[b * Dsz + (c - Esz)];
}

__global__ void gru_kernel(const float* __restrict__ hprev, float* __restrict__ hnew) {
    int b = blockIdx.x, h = threadIdx.x;
    int base = b * 3 * Hsz;
    float r = 1.f / (1.f + __expf(-(g_gi[base + h]       + g_gh[base + h])));
    float z = 1.f / (1.f + __expf(-(g_gi[base + Hsz + h] + g_gh[base + Hsz + h])));
    float n = tanhf(g_gi[base + 2 * Hsz + h] + r * g_gh[base + 2 * Hsz + h]);
    hnew[b * Hsz + h] = (1.f - z) * n + z * hprev[b * Hsz + h];
}

// ===========================================================================
extern "C" void kernel_launch(void* const* d_in, const int* in_sizes, int n_in,
                              void* d_out, int out_size)
{
    const float* embed  = (const float*)d_in[0];
    const float* hidden = (const float*)d_in[1];
    const float* enc    = (const float*)d_in[2];
    const float* Wq     = (const float*)d_in[3];
    const float* Wk     = (const float*)d_in[4];
    const float* av     = (const float*)d_in[5];
    const float* Wih0   = (const float*)d_in[6];
    const float* Whh0   = (const float*)d_in[7];
    const float* bih0   = (const float*)d_in[8];
    const float* bhh0   = (const float*)d_in[9];
    const float* Wih1   = (const float*)d_in[10];
    const float* Whh1   = (const float*)d_in[11];
    const float* bih1   = (const float*)d_in[12];
    const float* bhh1   = (const float*)d_in[13];
    const float* Wout   = (const float*)d_in[14];
    const float* bout   = (const float*)d_in[15];

    float* out_logits = (float*)d_out;
    float* out_hidden = out_logits + (size_t)Bsz * Vsz;
    float* out_attnw  = out_hidden + (size_t)2 * Bsz * Hsz;

    float *p_qproj, *p_x0, *p_gi, *p_gh;
    cudaGetSymbolAddress((void**)&p_qproj, g_qproj);
    cudaGetSymbolAddress((void**)&p_x0,    g_x0);
    cudaGetSymbolAddress((void**)&p_gi,    g_gi);
    cudaGetSymbolAddress((void**)&p_gh,    g_gh);

    cudaFuncSetAttribute(scores_mma_kernel,
                         cudaFuncAttributeMaxDynamicSharedMemorySize, SC_SMEM);

    const float* h0_prev = hidden;
    const float* h1_prev = hidden + (size_t)Bsz * Hsz;

    // 1) Wk bf16 split + query projection
    wk_split_kernel<<<(Hsz * Dsz + 255) / 256, 256>>>(Wk);
    gemm_bias_kernel<<<dim3(Hsz / 64, Bsz / 64), 256>>>(
        h1_prev, Wq, nullptr, p_qproj, Hsz, Hsz);

    // 2) attention scores (HMMA), softmax, context
    scores_mma_kernel<<<dim3(Lsz / 128, Bsz), 256, SC_SMEM>>>(enc, av, out_attnw);
    softmax_kernel<<<Bsz, 256>>>(out_attnw);
    context_kernel<<<Bsz, 256>>>(enc, out_attnw);

    // 3) GRU layer 0
    concat_kernel<<<(Bsz * (Esz + Dsz) + 255) / 256, 256>>>(embed);
    gemm_bias_kernel<<<dim3(384 / 64, Bsz / 64), 256>>>(
        p_x0, Wih0, bih0, p_gi, 3 * Hsz, Esz + Dsz);
    gemm_bias_kernel<<<dim3(384 / 64, Bsz / 64), 256>>>(
        h0_prev, Whh0, bhh0, p_gh, 3 * Hsz, Hsz);
    gru_kernel<<<Bsz, Hsz>>>(h0_prev, out_hidden);

    // 4) GRU layer 1
    gemm_bias_kernel<<<dim3(384 / 64, Bsz / 64), 256>>>(
        out_hidden, Wih1, bih1, p_gi, 3 * Hsz, Hsz);
    gemm_bias_kernel<<<dim3(384 / 64, Bsz / 64), 256>>>(
        h1_prev, Whh1, bhh1, p_gh, 3 * Hsz, Hsz);
    gru_kernel<<<Bsz, Hsz>>>(h1_prev, out_hidden + (size_t)Bsz * Hsz);

    // 5) output projection
    gemm_bias_kernel<<<dim3((Vsz + 63) / 64, Bsz / 64), 256>>>(
        out_hidden + (size_t)Bsz * Hsz, Wout, bout, out_logits, Vsz, Hsz);
}

// round 5
// speedup vs baseline: 1.9244x; 1.2285x over previous
#include <cuda_runtime.h>
#include <cuda_bf16.h>
#include <cstdint>

#define Bsz 2048
#define Lsz 512
#define Esz 64
#define Hsz 128
#define Dsz 256
#define Vsz 1000

#define SMEM_SWIZZLE_128B(off) ((off) ^ (((off) >> 3) & 0x70))

__device__ __forceinline__ uint32_t smem_to_u32(const void* p) {
    uint32_t a;
    asm("{ .reg .u64 t; cvta.to.shared.u64 t, %1; cvt.u32.u64 %0, t; }"
        : "=r"(a) : "l"(p));
    return a;
}

__device__ __forceinline__ void ldmat4(uint32_t* r, uint32_t addr) {
    asm volatile("ldmatrix.sync.aligned.m8n8.x4.shared.b16 {%0,%1,%2,%3}, [%4];"
                 : "=r"(r[0]), "=r"(r[1]), "=r"(r[2]), "=r"(r[3]) : "r"(addr));
}

__device__ __forceinline__ void mma16816(float* d, const uint32_t* a, uint32_t b0, uint32_t b1) {
    asm volatile("mma.sync.aligned.m16n8k16.row.col.f32.bf16.bf16.f32 "
                 "{%0,%1,%2,%3}, {%4,%5,%6,%7}, {%8,%9}, {%0,%1,%2,%3};"
                 : "+f"(d[0]), "+f"(d[1]), "+f"(d[2]), "+f"(d[3])
                 : "r"(a[0]), "r"(a[1]), "r"(a[2]), "r"(a[3]), "r"(b0), "r"(b1));
}

__device__ __forceinline__ void cp_async16(uint32_t saddr, const void* gaddr) {
    asm volatile("cp.async.ca.shared.global [%0], [%1], 16;"
                 :: "r"(saddr), "l"(gaddr));
}
#define CP_ASYNC_COMMIT() asm volatile("cp.async.commit_group;" ::: "memory")
#define CP_ASYNC_WAIT0()  asm volatile("cp.async.wait_group 0;"  ::: "memory")

// accurate fast tanh: exp + fast divide (MUFU), rel err ~1e-7
__device__ __forceinline__ float tanh_acc(float x) {
    float ax = fabsf(x);
    float t  = __expf(-2.f * ax);
    float r  = __fdividef(1.f - t, 1.f + t);
    return copysignf(r, x);
}

// ===========================================================================
// Scratch
// ===========================================================================
__device__ float g_qproj[Bsz * Hsz];
__device__ float g_ctx[Bsz * Dsz];
__device__ float g_x0[Bsz * (Esz + Dsz)];
__device__ float g_gi[Bsz * 3 * Hsz];
__device__ float g_gh[Bsz * 3 * Hsz];
__device__ __nv_bfloat16 g_wkHi[Hsz * Dsz];
__device__ __nv_bfloat16 g_wkLo[Hsz * Dsz];

// ---------------------------------------------------------------------------
__global__ void wk_split_kernel(const float* __restrict__ wk) {
    int i = blockIdx.x * blockDim.x + threadIdx.x;
    if (i < Hsz * Dsz) {
        float w = wk[i];
        __nv_bfloat16 hi = __float2bfloat16(w);
        g_wkHi[i] = hi;
        g_wkLo[i] = __float2bfloat16(w - __bfloat162float(hi));
    }
}

// ---------------------------------------------------------------------------
// Generic tiled fp32 GEMM: C[m,n] = sum_k A[m,k] * W[n,k] (+ bias[n])
// ---------------------------------------------------------------------------
__global__ __launch_bounds__(256) void gemm_bias_kernel(
    const float* __restrict__ A, const float* __restrict__ W,
    const float* __restrict__ bias, float* __restrict__ C, int N, int K)
{
    __shared__ float As[16][64];
    __shared__ float Ws[16][64];
    int t  = threadIdx.x;
    int m0 = blockIdx.y * 64;
    int n0 = blockIdx.x * 64;
    int tx = t & 15, ty = t >> 4;
    int lm = t >> 2, kv = t & 3;

    float acc[4][4] = {};
    for (int k0 = 0; k0 < K; k0 += 16) {
        float4 avv = *(const float4*)(A + (size_t)(m0 + lm) * K + k0 + kv * 4);
        As[kv*4+0][lm] = avv.x; As[kv*4+1][lm] = avv.y;
        As[kv*4+2][lm] = avv.z; As[kv*4+3][lm] = avv.w;
        float4 wv = make_float4(0.f, 0.f, 0.f, 0.f);
        if (n0 + lm < N)
            wv = *(const float4*)(W + (size_t)(n0 + lm) * K + k0 + kv * 4);
        Ws[kv*4+0][lm] = wv.x; Ws[kv*4+1][lm] = wv.y;
        Ws[kv*4+2][lm] = wv.z; Ws[kv*4+3][lm] = wv.w;
        __syncthreads();
        #pragma unroll
        for (int kk = 0; kk < 16; kk++) {
            float a[4];
            #pragma unroll
            for (int j = 0; j < 4; j++) a[j] = As[kk][ty * 4 + j];
            float4 bv = *(const float4*)&Ws[kk][tx * 4];
            #pragma unroll
            for (int j = 0; j < 4; j++) {
                acc[j][0] += a[j] * bv.x; acc[j][1] += a[j] * bv.y;
                acc[j][2] += a[j] * bv.z; acc[j][3] += a[j] * bv.w;
            }
        }
        __syncthreads();
    }
    #pragma unroll
    for (int j = 0; j < 4; j++) {
        int m = m0 + ty * 4 + j;
        #pragma unroll
        for (int i = 0; i < 4; i++) {
            int n = n0 + tx * 4 + i;
            if (n < N) {
                float v = acc[j][i];
                if (bias) v += bias[n];
                C[(size_t)m * N + n] = v;
            }
        }
    }
}

// ===========================================================================
// Scores via mma.sync bf16 3-term split, occupancy-2 for cross-CTA overlap.
// Block: 128 l x 128 h, K=256 in 4 chunks of 64.
// 8 warps as 4(row) x 2(col): warp tile 32 l x 64 h.
// ===========================================================================
#define SA_HI 0
#define SA_LO 16384
#define SB_HI 32768
#define SB_LO 49152
#define SC_SMEM 65536

__global__ __launch_bounds__(256, 2) void scores_mma_kernel(
    const float* __restrict__ enc, const float* __restrict__ attn_v,
    float* __restrict__ scores_out)
{
    extern __shared__ char smem[];
    __shared__ float qs[128], vs[128], sred[2][128];
    uint32_t sbase = smem_to_u32(smem);

    int t    = threadIdx.x;
    int lane = t & 31, w = t >> 5;
    int wr   = w & 3,  wc = w >> 2;
    int b    = blockIdx.y;
    int l0   = blockIdx.x * 128;

    if (t < 128) { qs[t] = g_qproj[b * Hsz + t]; vs[t] = attn_v[t]; }

    const float* encb = enc + (size_t)b * Lsz * Dsz + (size_t)l0 * Dsz;

    float acc[2][8][4];
    #pragma unroll
    for (int mt = 0; mt < 2; mt++)
        #pragma unroll
        for (int nt = 0; nt < 8; nt++)
            #pragma unroll
            for (int i = 0; i < 4; i++) acc[mt][nt][i] = 0.f;

    for (int c = 0; c < 4; c++) {
        int d0 = c * 64;
        // ---- B chunk via cp.async (no register round-trip) ----
        {
            // 16KB hi + 16KB lo per chunk; 256 thr * 4 * 16B each
            #pragma unroll
            for (int i = 0; i < 4; i++) {
                int idx = t + i * 256;          // 16B units, 8 per 128B row
                int row = idx >> 3;
                int u   = idx & 7;
                uint32_t off = SMEM_SWIZZLE_128B((uint32_t)(row * 128 + u * 16));
                cp_async16(sbase + SB_HI + off, g_wkHi + (size_t)row * Dsz + d0 + u * 8);
                cp_async16(sbase + SB_LO + off, g_wkLo + (size_t)row * Dsz + d0 + u * 8);
            }
            CP_ASYNC_COMMIT();
        }
        // ---- A chunk: fp32 load + bf16 hi/lo split (overlaps cp.async) ----
        #pragma unroll
        for (int i = 0; i < 8; i++) {
            int idx = t + i * 256;
            int row = idx >> 4;
            int dq  = idx & 15;
            float4 v4 = *(const float4*)(encb + (size_t)row * Dsz + d0 + dq * 4);
            __nv_bfloat16 h0 = __float2bfloat16(v4.x);
            __nv_bfloat16 h1 = __float2bfloat16(v4.y);
            __nv_bfloat16 h2 = __float2bfloat16(v4.z);
            __nv_bfloat16 h3 = __float2bfloat16(v4.w);
            __nv_bfloat16 r0 = __float2bfloat16(v4.x - __bfloat162float(h0));
            __nv_bfloat16 r1 = __float2bfloat16(v4.y - __bfloat162float(h1));
            __nv_bfloat16 r2 = __float2bfloat16(v4.z - __bfloat162float(h2));
            __nv_bfloat16 r3 = __float2bfloat16(v4.w - __bfloat162float(h3));
            uint32_t off = SMEM_SWIZZLE_128B((uint32_t)(row * 128 + dq * 8));
            uint2 hv, lv;
            hv.x = (uint32_t)__bfloat16_as_ushort(h0) | ((uint32_t)__bfloat16_as_ushort(h1) << 16);
            hv.y = (uint32_t)__bfloat16_as_ushort(h2) | ((uint32_t)__bfloat16_as_ushort(h3) << 16);
            lv.x = (uint32_t)__bfloat16_as_ushort(r0) | ((uint32_t)__bfloat16_as_ushort(r1) << 16);
            lv.y = (uint32_t)__bfloat16_as_ushort(r2) | ((uint32_t)__bfloat16_as_ushort(r3) << 16);
            *(uint2*)(smem + SA_HI + off) = hv;
            *(uint2*)(smem + SA_LO + off) = lv;
        }
        CP_ASYNC_WAIT0();
        __syncthreads();

        // ---- 4 k-steps of 16 within the chunk ----
        #pragma unroll
        for (int ks = 0; ks < 4; ks++) {
            int kb = ks * 32;
            uint32_t ah[2][4], al[2][4];
            #pragma unroll
            for (int mt = 0; mt < 2; mt++) {
                int row  = wr * 32 + mt * 16 + (lane & 15);
                int colb = kb + (lane >> 4) * 16;
                uint32_t off = SMEM_SWIZZLE_128B((uint32_t)(row * 128 + colb));
                ldmat4(ah[mt], sbase + SA_HI + off);
                ldmat4(al[mt], sbase + SA_LO + off);
            }
            // B fragments per 16-row group, consumed immediately (low reg pressure)
            #pragma unroll
            for (int p = 0; p < 4; p++) {
                int row  = wc * 64 + p * 16 + (lane & 15);
                int colb = kb + (lane >> 4) * 16;
                uint32_t off = SMEM_SWIZZLE_128B((uint32_t)(row * 128 + colb));
                uint32_t rh[4], rl[4];
                ldmat4(rh, sbase + SB_HI + off);
                ldmat4(rl, sbase + SB_LO + off);
                #pragma unroll
                for (int mt = 0; mt < 2; mt++) {
                    mma16816(acc[mt][p*2],   ah[mt], rh[0], rh[2]);
                    mma16816(acc[mt][p*2+1], ah[mt], rh[1], rh[3]);
                    mma16816(acc[mt][p*2],   al[mt], rh[0], rh[2]);
                    mma16816(acc[mt][p*2+1], al[mt], rh[1], rh[3]);
                    mma16816(acc[mt][p*2],   ah[mt], rl[0], rl[2]);
                    mma16816(acc[mt][p*2+1], ah[mt], rl[1], rl[3]);
                }
            }
        }
        __syncthreads();
    }

    // ---- epilogue: score[l] = sum_h v[h]*tanh(acc + qproj[h]) ----
    float part[4];
    #pragma unroll
    for (int mt = 0; mt < 2; mt++)
        #pragma unroll
        for (int half = 0; half < 2; half++) {
            float p = 0.f;
            #pragma unroll
            for (int nt = 0; nt < 8; nt++)
                #pragma unroll
                for (int j = 0; j < 2; j++) {
                    int h = wc * 64 + nt * 8 + (lane & 3) * 2 + j;
                    float e = acc[mt][nt][half * 2 + j] + qs[h];
                    p += vs[h] * tanh_acc(e);
                }
            part[mt * 2 + half] = p;
        }
    #pragma unroll
    for (int k = 0; k < 4; k++) {
        part[k] += __shfl_xor_sync(0xffffffffu, part[k], 1);
        part[k] += __shfl_xor_sync(0xffffffffu, part[k], 2);
    }
    if ((lane & 3) == 0) {
        #pragma unroll
        for (int mt = 0; mt < 2; mt++)
            #pragma unroll
            for (int half = 0; half < 2; half++) {
                int row = wr * 32 + mt * 16 + half * 8 + (lane >> 2);
                sred[wc][row] = part[mt * 2 + half];
            }
    }
    __syncthreads();
    if (t < 128)
        scores_out[(size_t)b * Lsz + l0 + t] = sred[0][t] + sred[1][t];
}

// ---------------------------------------------------------------------------
__global__ void softmax_kernel(float* __restrict__ w) {
    __shared__ float red[256];
    int b = blockIdx.x, t = threadIdx.x;
    float* wb = w + (size_t)b * Lsz;
    float v0 = wb[t], v1 = wb[t + 256];
    red[t] = fmaxf(v0, v1);
    __syncthreads();
    for (int s = 128; s > 0; s >>= 1) {
        if (t < s) red[t] = fmaxf(red[t], red[t + s]);
        __syncthreads();
    }
    float mx = red[0];
    __syncthreads();
    float e0 = __expf(v0 - mx), e1 = __expf(v1 - mx);
    red[t] = e0 + e1;
    __syncthreads();
    for (int s = 128; s > 0; s >>= 1) {
        if (t < s) red[t] += red[t + s];
        __syncthreads();
    }
    float inv = 1.f / red[0];
    wb[t] = e0 * inv;
    wb[t + 256] = e1 * inv;
}

// ---------------------------------------------------------------------------
__global__ __launch_bounds__(256) void context_kernel(
    const float* __restrict__ enc, const float* __restrict__ w)
{
    __shared__ float ws[Lsz];
    int b = blockIdx.x, t = threadIdx.x;
    ws[t]       = w[(size_t)b * Lsz + t];
    ws[t + 256] = w[(size_t)b * Lsz + t + 256];
    __syncthreads();
    const float* e = enc + (size_t)b * Lsz * Dsz + t;
    float acc = 0.f;
    #pragma unroll 8
    for (int l = 0; l < Lsz; l++) acc += ws[l] * e[(size_t)l * Dsz];
    g_ctx[b * Dsz + t] = acc;
}

__global__ void concat_kernel(const float* __restrict__ embed) {
    int i = blockIdx.x * blockDim.x + threadIdx.x;
    if (i >= Bsz * (Esz + Dsz)) return;
    int b = i / (Esz + Dsz), c = i - b * (Esz + Dsz);
    g_x0[i] = (c < Esz) ? embed[b * Esz + c] : g_ctx[b * Dsz + (c - Esz)];
}

__global__ void gru_kernel(const float* __restrict__ hprev, float* __restrict__ hnew) {
    int b = blockIdx.x, h = threadIdx.x;
    int base = b * 3 * Hsz;
    float r = 1.f / (1.f + __expf(-(g_gi[base + h]       + g_gh[base + h])));
    float z = 1.f / (1.f + __expf(-(g_gi[base + Hsz + h] + g_gh[base + Hsz + h])));
    float n = tanhf(g_gi[base + 2 * Hsz + h] + r * g_gh[base + 2 * Hsz + h]);
    hnew[b * Hsz + h] = (1.f - z) * n + z * hprev[b * Hsz + h];
}

// ===========================================================================
extern "C" void kernel_launch(void* const* d_in, const int* in_sizes, int n_in,
                              void* d_out, int out_size)
{
    const float* embed  = (const float*)d_in[0];
    const float* hidden = (const float*)d_in[1];
    const float* enc    = (const float*)d_in[2];
    const float* Wq     = (const float*)d_in[3];
    const float* Wk     = (const float*)d_in[4];
    const float* av     = (const float*)d_in[5];
    const float* Wih0   = (const float*)d_in[6];
    const float* Whh0   = (const float*)d_in[7];
    const float* bih0   = (const float*)d_in[8];
    const float* bhh0   = (const float*)d_in[9];
    const float* Wih1   = (const float*)d_in[10];
    const float* Whh1   = (const float*)d_in[11];
    const float* bih1   = (const float*)d_in[12];
    const float* bhh1   = (const float*)d_in[13];
    const float* Wout   = (const float*)d_in[14];
    const float* bout   = (const float*)d_in[15];

    float* out_logits = (float*)d_out;
    float* out_hidden = out_logits + (size_t)Bsz * Vsz;
    float* out_attnw  = out_hidden + (size_t)2 * Bsz * Hsz;

    float *p_qproj, *p_x0, *p_gi, *p_gh;
    cudaGetSymbolAddress((void**)&p_qproj, g_qproj);
    cudaGetSymbolAddress((void**)&p_x0,    g_x0);
    cudaGetSymbolAddress((void**)&p_gi,    g_gi);
    cudaGetSymbolAddress((void**)&p_gh,    g_gh);

    cudaFuncSetAttribute(scores_mma_kernel,
                         cudaFuncAttributeMaxDynamicSharedMemorySize, SC_SMEM);

    const float* h0_prev = hidden;
    const float* h1_prev = hidden + (size_t)Bsz * Hsz;

    // 1) Wk bf16 split + query projection
    wk_split_kernel<<<(Hsz * Dsz + 255) / 256, 256>>>(Wk);
    gemm_bias_kernel<<<dim3(Hsz / 64, Bsz / 64), 256>>>(
        h1_prev, Wq, nullptr, p_qproj, Hsz, Hsz);

    // 2) attention scores (HMMA, occ-2), softmax, context
    scores_mma_kernel<<<dim3(Lsz / 128, Bsz), 256, SC_SMEM>>>(enc, av, out_attnw);
    softmax_kernel<<<Bsz, 256>>>(out_attnw);
    context_kernel<<<Bsz, 256>>>(enc, out_attnw);

    // 3) GRU layer 0
    concat_kernel<<<(Bsz * (Esz + Dsz) + 255) / 256, 256>>>(embed);
    gemm_bias_kernel<<<dim3(384 / 64, Bsz / 64), 256>>>(
        p_x0, Wih0, bih0, p_gi, 3 * Hsz, Esz + Dsz);
    gemm_bias_kernel<<<dim3(384 / 64, Bsz / 64), 256>>>(
        h0_prev, Whh0, bhh0, p_gh, 3 * Hsz, Hsz);
    gru_kernel<<<Bsz, Hsz>>>(h0_prev, out_hidden);

    // 4) GRU layer 1
    gemm_bias_kernel<<<dim3(384 / 64, Bsz / 64), 256>>>(
        out_hidden, Wih1, bih1, p_gi, 3 * Hsz, Hsz);
    gemm_bias_kernel<<<dim3(384 / 64, Bsz / 64), 256>>>(
        h1_prev, Whh1, bhh1, p_gh, 3 * Hsz, Hsz);
    gru_kernel<<<Bsz, Hsz>>>(h1_prev, out_hidden + (size_t)Bsz * Hsz);

    // 5) output projection
    gemm_bias_kernel<<<dim3((Vsz + 63) / 64, Bsz / 64), 256>>>(
        out_hidden + (size_t)Bsz * Hsz, Wout, bout, out_logits, Vsz, Hsz);
}

// round 6
// speedup vs baseline: 2.2467x; 1.1675x over previous
#include <cuda_runtime.h>
#include <cuda_bf16.h>
#include <cuda_fp16.h>
#include <cstdint>

#define Bsz 2048
#define Lsz 512
#define Esz 64
#define Hsz 128
#define Dsz 256
#define Vsz 1000

#define SMEM_SWIZZLE_128B(off) ((off) ^ (((off) >> 3) & 0x70))

__device__ __forceinline__ uint32_t smem_to_u32(const void* p) {
    uint32_t a;
    asm("{ .reg .u64 t; cvta.to.shared.u64 t, %1; cvt.u32.u64 %0, t; }"
        : "=r"(a) : "l"(p));
    return a;
}

__device__ __forceinline__ void ldmat4(uint32_t* r, uint32_t addr) {
    asm volatile("ldmatrix.sync.aligned.m8n8.x4.shared.b16 {%0,%1,%2,%3}, [%4];"
                 : "=r"(r[0]), "=r"(r[1]), "=r"(r[2]), "=r"(r[3]) : "r"(addr));
}

// fp16 x fp16 -> fp32 mma (sm_80+, not arch-gated)
__device__ __forceinline__ void mma16816(float* d, const uint32_t* a, uint32_t b0, uint32_t b1) {
    asm volatile("mma.sync.aligned.m16n8k16.row.col.f32.f16.f16.f32 "
                 "{%0,%1,%2,%3}, {%4,%5,%6,%7}, {%8,%9}, {%0,%1,%2,%3};"
                 : "+f"(d[0]), "+f"(d[1]), "+f"(d[2]), "+f"(d[3])
                 : "r"(a[0]), "r"(a[1]), "r"(a[2]), "r"(a[3]), "r"(b0), "r"(b1));
}

__device__ __forceinline__ void cp_async16(uint32_t saddr, const void* gaddr) {
    asm volatile("cp.async.ca.shared.global [%0], [%1], 16;"
                 :: "r"(saddr), "l"(gaddr));
}
#define CP_ASYNC_COMMIT() asm volatile("cp.async.commit_group;" ::: "memory")
#define CP_ASYNC_WAIT0()  asm volatile("cp.async.wait_group 0;"  ::: "memory")

// accurate fast tanh (MUFU ex2 + fast div), rel err ~1e-7
__device__ __forceinline__ float tanh_acc(float x) {
    float ax = fabsf(x);
    float t  = __expf(-2.f * ax);
    float r  = __fdividef(1.f - t, 1.f + t);
    return copysignf(r, x);
}

// ===========================================================================
// Scratch
// ===========================================================================
__device__ float g_qproj[Bsz * Hsz];
__device__ float g_ctx[Bsz * Dsz];
__device__ float g_x0[Bsz * (Esz + Dsz)];
__device__ float g_gi[Bsz * 3 * Hsz];
__device__ float g_gh[Bsz * 3 * Hsz];
__device__ __half g_wkH[Hsz * Dsz];     // Wk in fp16 (single term)

// ---------------------------------------------------------------------------
__global__ void wk_split_kernel(const float* __restrict__ wk) {
    int i = blockIdx.x * blockDim.x + threadIdx.x;
    if (i < Hsz * Dsz) g_wkH[i] = __float2half_rn(wk[i]);
}

// ---------------------------------------------------------------------------
// Generic tiled fp32 GEMM: C[m,n] = sum_k A[m,k] * W[n,k] (+ bias[n])
// ---------------------------------------------------------------------------
__global__ __launch_bounds__(256) void gemm_bias_kernel(
    const float* __restrict__ A, const float* __restrict__ W,
    const float* __restrict__ bias, float* __restrict__ C, int N, int K)
{
    __shared__ float As[16][64];
    __shared__ float Ws[16][64];
    int t  = threadIdx.x;
    int m0 = blockIdx.y * 64;
    int n0 = blockIdx.x * 64;
    int tx = t & 15, ty = t >> 4;
    int lm = t >> 2, kv = t & 3;

    float acc[4][4] = {};
    for (int k0 = 0; k0 < K; k0 += 16) {
        float4 avv = *(const float4*)(A + (size_t)(m0 + lm) * K + k0 + kv * 4);
        As[kv*4+0][lm] = avv.x; As[kv*4+1][lm] = avv.y;
        As[kv*4+2][lm] = avv.z; As[kv*4+3][lm] = avv.w;
        float4 wv = make_float4(0.f, 0.f, 0.f, 0.f);
        if (n0 + lm < N)
            wv = *(const float4*)(W + (size_t)(n0 + lm) * K + k0 + kv * 4);
        Ws[kv*4+0][lm] = wv.x; Ws[kv*4+1][lm] = wv.y;
        Ws[kv*4+2][lm] = wv.z; Ws[kv*4+3][lm] = wv.w;
        __syncthreads();
        #pragma unroll
        for (int kk = 0; kk < 16; kk++) {
            float a[4];
            #pragma unroll
            for (int j = 0; j < 4; j++) a[j] = As[kk][ty * 4 + j];
            float4 bv = *(const float4*)&Ws[kk][tx * 4];
            #pragma unroll
            for (int j = 0; j < 4; j++) {
                acc[j][0] += a[j] * bv.x; acc[j][1] += a[j] * bv.y;
                acc[j][2] += a[j] * bv.z; acc[j][3] += a[j] * bv.w;
            }
        }
        __syncthreads();
    }
    #pragma unroll
    for (int j = 0; j < 4; j++) {
        int m = m0 + ty * 4 + j;
        #pragma unroll
        for (int i = 0; i < 4; i++) {
            int n = n0 + tx * 4 + i;
            if (n < N) {
                float v = acc[j][i];
                if (bias) v += bias[n];
                C[(size_t)m * N + n] = v;
            }
        }
    }
}

// ===========================================================================
// Scores, fp16 2-term split (A=hi+lo fp16, B=Wk single fp16 resident in smem).
// Block: 128 l x 128 h, K=256 in 4 chunks of 64.
// 8 warps as 4(row) x 2(col): warp tile 32 l x 64 h.
// Smem: SB (all of Wk, 64KB, 512B rows XOR-swizzled) + SA hi/lo (16KB each).
// ===========================================================================
#define SB_OFF 0
#define SA_HI  65536
#define SA_LO  (65536 + 16384)
#define SC_SMEM (65536 + 32768)

__global__ __launch_bounds__(256, 2) void scores_mma_kernel(
    const float* __restrict__ enc, const float* __restrict__ attn_v,
    float* __restrict__ scores_out)
{
    extern __shared__ char smem[];
    __shared__ float qs[128], vs[128], sred[2][128];
    uint32_t sbase = smem_to_u32(smem);

    int t    = threadIdx.x;
    int lane = t & 31, w = t >> 5;
    int wr   = w & 3,  wc = w >> 2;
    int b    = blockIdx.y;
    int l0   = blockIdx.x * 128;

    // ---- B: load ALL of Wk fp16 once (64KB), 512B rows, XOR swizzle ----
    #pragma unroll
    for (int i = 0; i < 16; i++) {
        int u   = t + i * 256;           // 16B units, 32 per row
        int row = u >> 5;
        int cu  = u & 31;
        uint32_t dst = sbase + SB_OFF + (uint32_t)(row * 512 + ((cu ^ (row & 7)) << 4));
        cp_async16(dst, g_wkH + (size_t)row * Dsz + cu * 8);
    }
    CP_ASYNC_COMMIT();

    if (t < 128) { qs[t] = g_qproj[b * Hsz + t]; vs[t] = attn_v[t]; }

    const float* encb = enc + (size_t)b * Lsz * Dsz + (size_t)l0 * Dsz;

    float acc[2][8][4];
    #pragma unroll
    for (int mt = 0; mt < 2; mt++)
        #pragma unroll
        for (int nt = 0; nt < 8; nt++)
            #pragma unroll
            for (int i = 0; i < 4; i++) acc[mt][nt][i] = 0.f;

    for (int c = 0; c < 4; c++) {
        int d0 = c * 64;
        // ---- A chunk: fp32 load + fp16 hi/lo split, 128B rows SW128 ----
        #pragma unroll
        for (int i = 0; i < 8; i++) {
            int idx = t + i * 256;
            int row = idx >> 4;
            int dq  = idx & 15;
            float4 v4 = *(const float4*)(encb + (size_t)row * Dsz + d0 + dq * 4);
            __half h0 = __float2half_rn(v4.x);
            __half h1 = __float2half_rn(v4.y);
            __half h2 = __float2half_rn(v4.z);
            __half h3 = __float2half_rn(v4.w);
            __half r0 = __float2half_rn(v4.x - __half2float(h0));
            __half r1 = __float2half_rn(v4.y - __half2float(h1));
            __half r2 = __float2half_rn(v4.z - __half2float(h2));
            __half r3 = __float2half_rn(v4.w - __half2float(h3));
            uint32_t off = SMEM_SWIZZLE_128B((uint32_t)(row * 128 + dq * 8));
            uint2 hv, lv;
            hv.x = (uint32_t)__half_as_ushort(h0) | ((uint32_t)__half_as_ushort(h1) << 16);
            hv.y = (uint32_t)__half_as_ushort(h2) | ((uint32_t)__half_as_ushort(h3) << 16);
            lv.x = (uint32_t)__half_as_ushort(r0) | ((uint32_t)__half_as_ushort(r1) << 16);
            lv.y = (uint32_t)__half_as_ushort(r2) | ((uint32_t)__half_as_ushort(r3) << 16);
            *(uint2*)(smem + SA_HI + off) = hv;
            *(uint2*)(smem + SA_LO + off) = lv;
        }
        if (c == 0) CP_ASYNC_WAIT0();   // B resident from here on
        __syncthreads();

        // ---- 4 k-steps of 16 within the chunk ----
        #pragma unroll
        for (int ks = 0; ks < 4; ks++) {
            int kb = ks * 32;           // byte offset within 128B A row
            uint32_t ah[2][4], al[2][4];
            #pragma unroll
            for (int mt = 0; mt < 2; mt++) {
                int row  = wr * 32 + mt * 16 + (lane & 15);
                int colb = kb + (lane >> 4) * 16;
                uint32_t off = SMEM_SWIZZLE_128B((uint32_t)(row * 128 + colb));
                ldmat4(ah[mt], sbase + SA_HI + off);
                ldmat4(al[mt], sbase + SA_LO + off);
            }
            #pragma unroll
            for (int p = 0; p < 4; p++) {
                int row  = wc * 64 + p * 16 + (lane & 15);
                int colb = c * 128 + kb + (lane >> 4) * 16;   // global d bytes
                uint32_t off = (uint32_t)(row * 512) +
                               ((((uint32_t)colb >> 4) ^ (uint32_t)(row & 7)) << 4);
                uint32_t rb[4];
                ldmat4(rb, sbase + SB_OFF + off);
                #pragma unroll
                for (int mt = 0; mt < 2; mt++) {
                    mma16816(acc[mt][p*2],   ah[mt], rb[0], rb[2]);
                    mma16816(acc[mt][p*2+1], ah[mt], rb[1], rb[3]);
                    mma16816(acc[mt][p*2],   al[mt], rb[0], rb[2]);
                    mma16816(acc[mt][p*2+1], al[mt], rb[1], rb[3]);
                }
            }
        }
        __syncthreads();
    }

    // ---- epilogue: score[l] = sum_h v[h]*tanh(acc + qproj[h]) ----
    float part[4];
    #pragma unroll
    for (int mt = 0; mt < 2; mt++)
        #pragma unroll
        for (int half = 0; half < 2; half++) {
            float p = 0.f;
            #pragma unroll
            for (int nt = 0; nt < 8; nt++)
                #pragma unroll
                for (int j = 0; j < 2; j++) {
                    int h = wc * 64 + nt * 8 + (lane & 3) * 2 + j;
                    float e = acc[mt][nt][half * 2 + j] + qs[h];
                    p += vs[h] * tanh_acc(e);
                }
            part[mt * 2 + half] = p;
        }
    #pragma unroll
    for (int k = 0; k < 4; k++) {
        part[k] += __shfl_xor_sync(0xffffffffu, part[k], 1);
        part[k] += __shfl_xor_sync(0xffffffffu, part[k], 2);
    }
    if ((lane & 3) == 0) {
        #pragma unroll
        for (int mt = 0; mt < 2; mt++)
            #pragma unroll
            for (int half = 0; half < 2; half++) {
                int row = wr * 32 + mt * 16 + half * 8 + (lane >> 2);
                sred[wc][row] = part[mt * 2 + half];
            }
    }
    __syncthreads();
    if (t < 128)
        scores_out[(size_t)b * Lsz + l0 + t] = sred[0][t] + sred[1][t];
}

// ---------------------------------------------------------------------------
__global__ void softmax_kernel(float* __restrict__ w) {
    __shared__ float red[256];
    int b = blockIdx.x, t = threadIdx.x;
    float* wb = w + (size_t)b * Lsz;
    float v0 = wb[t], v1 = wb[t + 256];
    red[t] = fmaxf(v0, v1);
    __syncthreads();
    for (int s = 128; s > 0; s >>= 1) {
        if (t < s) red[t] = fmaxf(red[t], red[t + s]);
        __syncthreads();
    }
    float mx = red[0];
    __syncthreads();
    float e0 = __expf(v0 - mx), e1 = __expf(v1 - mx);
    red[t] = e0 + e1;
    __syncthreads();
    for (int s = 128; s > 0; s >>= 1) {
        if (t < s) red[t] += red[t + s];
        __syncthreads();
    }
    float inv = 1.f / red[0];
    wb[t] = e0 * inv;
    wb[t + 256] = e1 * inv;
}

// ---------------------------------------------------------------------------
__global__ __launch_bounds__(256) void context_kernel(
    const float* __restrict__ enc, const float* __restrict__ w)
{
    __shared__ float ws[Lsz];
    int b = blockIdx.x, t = threadIdx.x;
    ws[t]       = w[(size_t)b * Lsz + t];
    ws[t + 256] = w[(size_t)b * Lsz + t + 256];
    __syncthreads();
    const float* e = enc + (size_t)b * Lsz * Dsz + t;
    float acc = 0.f;
    #pragma unroll 8
    for (int l = 0; l < Lsz; l++) acc += ws[l] * e[(size_t)l * Dsz];
    g_ctx[b * Dsz + t] = acc;
}

__global__ void concat_kernel(const float* __restrict__ embed) {
    int i = blockIdx.x * blockDim.x + threadIdx.x;
    if (i >= Bsz * (Esz + Dsz)) return;
    int b = i / (Esz + Dsz), c = i - b * (Esz + Dsz);
    g_x0[i] = (c < Esz) ? embed[b * Esz + c] : g_ctx[b * Dsz + (c - Esz)];
}

__global__ void gru_kernel(const float* __restrict__ hprev, float* __restrict__ hnew) {
    int b = blockIdx.x, h = threadIdx.x;
    int base = b * 3 * Hsz;
    float r = 1.f / (1.f + __expf(-(g_gi[base + h]       + g_gh[base + h])));
    float z = 1.f / (1.f + __expf(-(g_gi[base + Hsz + h] + g_gh[base + Hsz + h])));
    float n = tanhf(g_gi[base + 2 * Hsz + h] + r * g_gh[base + 2 * Hsz + h]);
    hnew[b * Hsz + h] = (1.f - z) * n + z * hprev[b * Hsz + h];
}

// ===========================================================================
extern "C" void kernel_launch(void* const* d_in, const int* in_sizes, int n_in,
                              void* d_out, int out_size)
{
    const float* embed  = (const float*)d_in[0];
    const float* hidden = (const float*)d_in[1];
    const float* enc    = (const float*)d_in[2];
    const float* Wq     = (const float*)d_in[3];
    const float* Wk     = (const float*)d_in[4];
    const float* av     = (const float*)d_in[5];
    const float* Wih0   = (const float*)d_in[6];
    const float* Whh0   = (const float*)d_in[7];
    const float* bih0   = (const float*)d_in[8];
    const float* bhh0   = (const float*)d_in[9];
    const float* Wih1   = (const float*)d_in[10];
    const float* Whh1   = (const float*)d_in[11];
    const float* bih1   = (const float*)d_in[12];
    const float* bhh1   = (const float*)d_in[13];
    const float* Wout   = (const float*)d_in[14];
    const float* bout   = (const float*)d_in[15];

    float* out_logits = (float*)d_out;
    float* out_hidden = out_logits + (size_t)Bsz * Vsz;
    float* out_attnw  = out_hidden + (size_t)2 * Bsz * Hsz;

    float *p_qproj, *p_x0, *p_gi, *p_gh;
    cudaGetSymbolAddress((void**)&p_qproj, g_qproj);
    cudaGetSymbolAddress((void**)&p_x0,    g_x0);
    cudaGetSymbolAddress((void**)&p_gi,    g_gi);
    cudaGetSymbolAddress((void**)&p_gh,    g_gh);

    cudaFuncSetAttribute(scores_mma_kernel,
                         cudaFuncAttributeMaxDynamicSharedMemorySize, SC_SMEM);

    const float* h0_prev = hidden;
    const float* h1_prev = hidden + (size_t)Bsz * Hsz;

    // 1) Wk fp16 + query projection
    wk_split_kernel<<<(Hsz * Dsz + 255) / 256, 256>>>(Wk);
    gemm_bias_kernel<<<dim3(Hsz / 64, Bsz / 64), 256>>>(
        h1_prev, Wq, nullptr, p_qproj, Hsz, Hsz);

    // 2) attention scores (fp16 HMMA 2-term), softmax, context
    scores_mma_kernel<<<dim3(Lsz / 128, Bsz), 256, SC_SMEM>>>(enc, av, out_attnw);
    softmax_kernel<<<Bsz, 256>>>(out_attnw);
    context_kernel<<<Bsz, 256>>>(enc, out_attnw);

    // 3) GRU layer 0
    concat_kernel<<<(Bsz * (Esz + Dsz) + 255) / 256, 256>>>(embed);
    gemm_bias_kernel<<<dim3(384 / 64, Bsz / 64), 256>>>(
        p_x0, Wih0, bih0, p_gi, 3 * Hsz, Esz + Dsz);
    gemm_bias_kernel<<<dim3(384 / 64, Bsz / 64), 256>>>(
        h0_prev, Whh0, bhh0, p_gh, 3 * Hsz, Hsz);
    gru_kernel<<<Bsz, Hsz>>>(h0_prev, out_hidden);

    // 4) GRU layer 1
    gemm_bias_kernel<<<dim3(384 / 64, Bsz / 64), 256>>>(
        out_hidden, Wih1, bih1, p_gi, 3 * Hsz, Hsz);
    gemm_bias_kernel<<<dim3(384 / 64, Bsz / 64), 256>>>(
        h1_prev, Whh1, bhh1, p_gh, 3 * Hsz, Hsz);
    gru_kernel<<<Bsz, Hsz>>>(h1_prev, out_hidden + (size_t)Bsz * Hsz);

    // 5) output projection
    gemm_bias_kernel<<<dim3((Vsz + 63) / 64, Bsz / 64), 256>>>(
        out_hidden + (size_t)Bsz * Hsz, Wout, bout, out_logits, Vsz, Hsz);
}

// round 7
// speedup vs baseline: 2.8422x; 1.2650x over previous
#include <cuda_runtime.h>
#include <cuda_bf16.h>
#include <cuda_fp16.h>
#include <cstdint>

#define Bsz 2048
#define Lsz 512
#define Esz 64
#define Hsz 128
#define Dsz 256
#define Vsz 1000

#define SMEM_SWIZZLE_128B(off) ((off) ^ (((off) >> 3) & 0x70))

__device__ __forceinline__ uint32_t smem_to_u32(const void* p) {
    uint32_t a;
    asm("{ .reg .u64 t; cvta.to.shared.u64 t, %1; cvt.u32.u64 %0, t; }"
        : "=r"(a) : "l"(p));
    return a;
}

__device__ __forceinline__ void ldmat4(uint32_t* r, uint32_t addr) {
    asm volatile("ldmatrix.sync.aligned.m8n8.x4.shared.b16 {%0,%1,%2,%3}, [%4];"
                 : "=r"(r[0]), "=r"(r[1]), "=r"(r[2]), "=r"(r[3]) : "r"(addr));
}

__device__ __forceinline__ void mma16816(float* d, const uint32_t* a, uint32_t b0, uint32_t b1) {
    asm volatile("mma.sync.aligned.m16n8k16.row.col.f32.f16.f16.f32 "
                 "{%0,%1,%2,%3}, {%4,%5,%6,%7}, {%8,%9}, {%0,%1,%2,%3};"
                 : "+f"(d[0]), "+f"(d[1]), "+f"(d[2]), "+f"(d[3])
                 : "r"(a[0]), "r"(a[1]), "r"(a[2]), "r"(a[3]), "r"(b0), "r"(b1));
}

__device__ __forceinline__ void cp_async16(uint32_t saddr, const void* gaddr) {
    asm volatile("cp.async.ca.shared.global [%0], [%1], 16;"
                 :: "r"(saddr), "l"(gaddr));
}
#define CP_ASYNC_COMMIT() asm volatile("cp.async.commit_group;" ::: "memory")
#define CP_ASYNC_WAIT0()  asm volatile("cp.async.wait_group 0;"  ::: "memory")

// accurate fast tanh (MUFU ex2 + fast div), rel err ~1e-7
__device__ __forceinline__ float tanh_acc(float x) {
    float ax = fabsf(x);
    float t  = __expf(-2.f * ax);
    float r  = __fdividef(1.f - t, 1.f + t);
    return copysignf(r, x);
}

// ===========================================================================
// Scratch
// ===========================================================================
__device__ float g_qproj[Bsz * Hsz];
__device__ float g_ctx[Bsz * Dsz];
__device__ float g_x0[Bsz * (Esz + Dsz)];
__device__ float g_gi[Bsz * 3 * Hsz];
__device__ float g_gh[Bsz * 3 * Hsz];
__device__ __half g_wkH[Hsz * Dsz];     // Wk fp16

// ---------------------------------------------------------------------------
__global__ void wk_split_kernel(const float* __restrict__ wk) {
    int i = blockIdx.x * blockDim.x + threadIdx.x;
    if (i < Hsz * Dsz) g_wkH[i] = __float2half_rn(wk[i]);
}

// ---------------------------------------------------------------------------
// Generic tiled fp32 GEMM: C[m,n] = sum_k A[m,k] * W[n,k] (+ bias[n])
// ---------------------------------------------------------------------------
__global__ __launch_bounds__(256) void gemm_bias_kernel(
    const float* __restrict__ A, const float* __restrict__ W,
    const float* __restrict__ bias, float* __restrict__ C, int N, int K)
{
    __shared__ float As[16][64];
    __shared__ float Ws[16][64];
    int t  = threadIdx.x;
    int m0 = blockIdx.y * 64;
    int n0 = blockIdx.x * 64;
    int tx = t & 15, ty = t >> 4;
    int lm = t >> 2, kv = t & 3;

    float acc[4][4] = {};
    for (int k0 = 0; k0 < K; k0 += 16) {
        float4 avv = *(const float4*)(A + (size_t)(m0 + lm) * K + k0 + kv * 4);
        As[kv*4+0][lm] = avv.x; As[kv*4+1][lm] = avv.y;
        As[kv*4+2][lm] = avv.z; As[kv*4+3][lm] = avv.w;
        float4 wv = make_float4(0.f, 0.f, 0.f, 0.f);
        if (n0 + lm < N)
            wv = *(const float4*)(W + (size_t)(n0 + lm) * K + k0 + kv * 4);
        Ws[kv*4+0][lm] = wv.x; Ws[kv*4+1][lm] = wv.y;
        Ws[kv*4+2][lm] = wv.z; Ws[kv*4+3][lm] = wv.w;
        __syncthreads();
        #pragma unroll
        for (int kk = 0; kk < 16; kk++) {
            float a[4];
            #pragma unroll
            for (int j = 0; j < 4; j++) a[j] = As[kk][ty * 4 + j];
            float4 bv = *(const float4*)&Ws[kk][tx * 4];
            #pragma unroll
            for (int j = 0; j < 4; j++) {
                acc[j][0] += a[j] * bv.x; acc[j][1] += a[j] * bv.y;
                acc[j][2] += a[j] * bv.z; acc[j][3] += a[j] * bv.w;
            }
        }
        __syncthreads();
    }
    #pragma unroll
    for (int j = 0; j < 4; j++) {
        int m = m0 + ty * 4 + j;
        #pragma unroll
        for (int i = 0; i < 4; i++) {
            int n = n0 + tx * 4 + i;
            if (n < N) {
                float v = acc[j][i];
                if (bias) v += bias[n];
                C[(size_t)m * N + n] = v;
            }
        }
    }
}

// ===========================================================================
// Scores, single-term fp16 (A fp16, B=Wk fp16 resident in smem).
// Block: 128 l x 128 h, K=256 in 4 chunks of 64.
// 8 warps as 4(row) x 2(col): warp tile 32 l x 64 h.
// Smem: SB (all Wk, 64KB, 512B-row XOR swizzle) + SA (16KB, SW128).
// ===========================================================================
#define SB_OFF 0
#define SA_OFF 65536
#define SC_SMEM (65536 + 16384)

__global__ __launch_bounds__(256, 2) void scores_mma_kernel(
    const float* __restrict__ enc, const float* __restrict__ attn_v,
    float* __restrict__ scores_out)
{
    extern __shared__ char smem[];
    __shared__ float qs[128], vs[128], sred[2][128];
    uint32_t sbase = smem_to_u32(smem);

    int t    = threadIdx.x;
    int lane = t & 31, w = t >> 5;
    int wr   = w & 3,  wc = w >> 2;
    int b    = blockIdx.y;
    int l0   = blockIdx.x * 128;

    // ---- B: load ALL of Wk fp16 once (64KB), 512B rows, XOR swizzle ----
    #pragma unroll
    for (int i = 0; i < 16; i++) {
        int u   = t + i * 256;           // 16B units, 32 per row
        int row = u >> 5;
        int cu  = u & 31;
        uint32_t dst = sbase + SB_OFF + (uint32_t)(row * 512 + ((cu ^ (row & 7)) << 4));
        cp_async16(dst, g_wkH + (size_t)row * Dsz + cu * 8);
    }
    CP_ASYNC_COMMIT();

    if (t < 128) { qs[t] = g_qproj[b * Hsz + t]; vs[t] = attn_v[t]; }

    const float* encb = enc + (size_t)b * Lsz * Dsz + (size_t)l0 * Dsz;

    float acc[2][8][4];
    #pragma unroll
    for (int mt = 0; mt < 2; mt++)
        #pragma unroll
        for (int nt = 0; nt < 8; nt++)
            #pragma unroll
            for (int i = 0; i < 4; i++) acc[mt][nt][i] = 0.f;

    for (int c = 0; c < 4; c++) {
        int d0 = c * 64;
        // ---- A chunk: fp32 load -> fp16, 128B rows SW128 ----
        #pragma unroll
        for (int i = 0; i < 8; i++) {
            int idx = t + i * 256;
            int row = idx >> 4;
            int dq  = idx & 15;
            float4 v4 = *(const float4*)(encb + (size_t)row * Dsz + d0 + dq * 4);
            __half2 p01 = __floats2half2_rn(v4.x, v4.y);
            __half2 p23 = __floats2half2_rn(v4.z, v4.w);
            uint32_t off = SMEM_SWIZZLE_128B((uint32_t)(row * 128 + dq * 8));
            uint2 hv;
            hv.x = *(uint32_t*)&p01;
            hv.y = *(uint32_t*)&p23;
            *(uint2*)(smem + SA_OFF + off) = hv;
        }
        if (c == 0) CP_ASYNC_WAIT0();   // B resident from here on
        __syncthreads();

        // ---- 4 k-steps of 16 within the chunk ----
        #pragma unroll
        for (int ks = 0; ks < 4; ks++) {
            int kb = ks * 32;           // byte offset within 128B A row
            uint32_t ah[2][4];
            #pragma unroll
            for (int mt = 0; mt < 2; mt++) {
                int row  = wr * 32 + mt * 16 + (lane & 15);
                int colb = kb + (lane >> 4) * 16;
                uint32_t off = SMEM_SWIZZLE_128B((uint32_t)(row * 128 + colb));
                ldmat4(ah[mt], sbase + SA_OFF + off);
            }
            #pragma unroll
            for (int p = 0; p < 4; p++) {
                int row  = wc * 64 + p * 16 + (lane & 15);
                int colb = c * 128 + kb + (lane >> 4) * 16;   // global d bytes
                uint32_t off = (uint32_t)(row * 512) +
                               ((((uint32_t)colb >> 4) ^ (uint32_t)(row & 7)) << 4);
                uint32_t rb[4];
                ldmat4(rb, sbase + SB_OFF + off);
                #pragma unroll
                for (int mt = 0; mt < 2; mt++) {
                    mma16816(acc[mt][p*2],   ah[mt], rb[0], rb[2]);
                    mma16816(acc[mt][p*2+1], ah[mt], rb[1], rb[3]);
                }
            }
        }
        __syncthreads();
    }

    // ---- epilogue: score[l] = sum_h v[h]*tanh(acc + qproj[h]) ----
    float part[4];
    #pragma unroll
    for (int mt = 0; mt < 2; mt++)
        #pragma unroll
        for (int half = 0; half < 2; half++) {
            float p = 0.f;
            #pragma unroll
            for (int nt = 0; nt < 8; nt++)
                #pragma unroll
                for (int j = 0; j < 2; j++) {
                    int h = wc * 64 + nt * 8 + (lane & 3) * 2 + j;
                    float e = acc[mt][nt][half * 2 + j] + qs[h];
                    p += vs[h] * tanh_acc(e);
                }
            part[mt * 2 + half] = p;
        }
    #pragma unroll
    for (int k = 0; k < 4; k++) {
        part[k] += __shfl_xor_sync(0xffffffffu, part[k], 1);
        part[k] += __shfl_xor_sync(0xffffffffu, part[k], 2);
    }
    if ((lane & 3) == 0) {
        #pragma unroll
        for (int mt = 0; mt < 2; mt++)
            #pragma unroll
            for (int half = 0; half < 2; half++) {
                int row = wr * 32 + mt * 16 + half * 8 + (lane >> 2);
                sred[wc][row] = part[mt * 2 + half];
            }
    }
    __syncthreads();
    if (t < 128)
        scores_out[(size_t)b * Lsz + l0 + t] = sred[0][t] + sred[1][t];
}

// ---------------------------------------------------------------------------
__global__ void softmax_kernel(float* __restrict__ w) {
    __shared__ float red[256];
    int b = blockIdx.x, t = threadIdx.x;
    float* wb = w + (size_t)b * Lsz;
    float v0 = wb[t], v1 = wb[t + 256];
    red[t] = fmaxf(v0, v1);
    __syncthreads();
    for (int s = 128; s > 0; s >>= 1) {
        if (t < s) red[t] = fmaxf(red[t], red[t + s]);
        __syncthreads();
    }
    float mx = red[0];
    __syncthreads();
    float e0 = __expf(v0 - mx), e1 = __expf(v1 - mx);
    red[t] = e0 + e1;
    __syncthreads();
    for (int s = 128; s > 0; s >>= 1) {
        if (t < s) red[t] += red[t + s];
        __syncthreads();
    }
    float inv = 1.f / red[0];
    wb[t] = e0 * inv;
    wb[t + 256] = e1 * inv;
}

// ---------------------------------------------------------------------------
__global__ __launch_bounds__(256) void context_kernel(
    const float* __restrict__ enc, const float* __restrict__ w)
{
    __shared__ float ws[Lsz];
    int b = blockIdx.x, t = threadIdx.x;
    ws[t]       = w[(size_t)b * Lsz + t];
    ws[t + 256] = w[(size_t)b * Lsz + t + 256];
    __syncthreads();
    const float* e = enc + (size_t)b * Lsz * Dsz + t;
    float acc = 0.f;
    #pragma unroll 8
    for (int l = 0; l < Lsz; l++) acc += ws[l] * e[(size_t)l * Dsz];
    g_ctx[b * Dsz + t] = acc;
}

__global__ void concat_kernel(const float* __restrict__ embed) {
    int i = blockIdx.x * blockDim.x + threadIdx.x;
    if (i >= Bsz * (Esz + Dsz)) return;
    int b = i / (Esz + Dsz), c = i - b * (Esz + Dsz);
    g_x0[i] = (c < Esz) ? embed[b * Esz + c] : g_ctx[b * Dsz + (c - Esz)];
}

__global__ void gru_kernel(const float* __restrict__ hprev, float* __restrict__ hnew) {
    int b = blockIdx.x, h = threadIdx.x;
    int base = b * 3 * Hsz;
    float r = 1.f / (1.f + __expf(-(g_gi[base + h]       + g_gh[base + h])));
    float z = 1.f / (1.f + __expf(-(g_gi[base + Hsz + h] + g_gh[base + Hsz + h])));
    float n = tanhf(g_gi[base + 2 * Hsz + h] + r * g_gh[base + 2 * Hsz + h]);
    hnew[b * Hsz + h] = (1.f - z) * n + z * hprev[b * Hsz + h];
}

// ===========================================================================
extern "C" void kernel_launch(void* const* d_in, const int* in_sizes, int n_in,
                              void* d_out, int out_size)
{
    const float* embed  = (const float*)d_in[0];
    const float* hidden = (const float*)d_in[1];
    const float* enc    = (const float*)d_in[2];
    const float* Wq     = (const float*)d_in[3];
    const float* Wk     = (const float*)d_in[4];
    const float* av     = (const float*)d_in[5];
    const float* Wih0   = (const float*)d_in[6];
    const float* Whh0   = (const float*)d_in[7];
    const float* bih0   = (const float*)d_in[8];
    const float* bhh0   = (const float*)d_in[9];
    const float* Wih1   = (const float*)d_in[10];
    const float* Whh1   = (const float*)d_in[11];
    const float* bih1   = (const float*)d_in[12];
    const float* bhh1   = (const float*)d_in[13];
    const float* Wout   = (const float*)d_in[14];
    const float* bout   = (const float*)d_in[15];

    float* out_logits = (float*)d_out;
    float* out_hidden = out_logits + (size_t)Bsz * Vsz;
    float* out_attnw  = out_hidden + (size_t)2 * Bsz * Hsz;

    float *p_qproj, *p_x0, *p_gi, *p_gh;
    cudaGetSymbolAddress((void**)&p_qproj, g_qproj);
    cudaGetSymbolAddress((void**)&p_x0,    g_x0);
    cudaGetSymbolAddress((void**)&p_gi,    g_gi);
    cudaGetSymbolAddress((void**)&p_gh,    g_gh);

    cudaFuncSetAttribute(scores_mma_kernel,
                         cudaFuncAttributeMaxDynamicSharedMemorySize, SC_SMEM);

    const float* h0_prev = hidden;
    const float* h1_prev = hidden + (size_t)Bsz * Hsz;

    // 1) Wk fp16 + query projection
    wk_split_kernel<<<(Hsz * Dsz + 255) / 256, 256>>>(Wk);
    gemm_bias_kernel<<<dim3(Hsz / 64, Bsz / 64), 256>>>(
        h1_prev, Wq, nullptr, p_qproj, Hsz, Hsz);

    // 2) attention scores (single-term fp16 HMMA), softmax, context
    scores_mma_kernel<<<dim3(Lsz / 128, Bsz), 256, SC_SMEM>>>(enc, av, out_attnw);
    softmax_kernel<<<Bsz, 256>>>(out_attnw);
    context_kernel<<<Bsz, 256>>>(enc, out_attnw);

    // 3) GRU layer 0
    concat_kernel<<<(Bsz * (Esz + Dsz) + 255) / 256, 256>>>(embed);
    gemm_bias_kernel<<<dim3(384 / 64, Bsz / 64), 256>>>(
        p_x0, Wih0, bih0, p_gi, 3 * Hsz, Esz + Dsz);
    gemm_bias_kernel<<<dim3(384 / 64, Bsz / 64), 256>>>(
        h0_prev, Whh0, bhh0, p_gh, 3 * Hsz, Hsz);
    gru_kernel<<<Bsz, Hsz>>>(h0_prev, out_hidden);

    // 4) GRU layer 1
    gemm_bias_kernel<<<dim3(384 / 64, Bsz / 64), 256>>>(
        out_hidden, Wih1, bih1, p_gi, 3 * Hsz, Hsz);
    gemm_bias_kernel<<<dim3(384 / 64, Bsz / 64), 256>>>(
        h1_prev, Whh1, bhh1, p_gh, 3 * Hsz, Hsz);
    gru_kernel<<<Bsz, Hsz>>>(h1_prev, out_hidden + (size_t)Bsz * Hsz);

    // 5) output projection
    gemm_bias_kernel<<<dim3((Vsz + 63) / 64, Bsz / 64), 256>>>(
        out_hidden + (size_t)Bsz * Hsz, Wout, bout, out_logits, Vsz, Hsz);
}

// round 8
// speedup vs baseline: 3.3900x; 1.1927x over previous
#include <cuda_runtime.h>
#include <cuda_bf16.h>
#include <cuda_fp16.h>
#include <cstdint>

#define Bsz 2048
#define Lsz 512
#define Esz 64
#define Hsz 128
#define Dsz 256
#define Vsz 1000

__device__ __forceinline__ uint32_t smem_to_u32(const void* p) {
    uint32_t a;
    asm("{ .reg .u64 t; cvta.to.shared.u64 t, %1; cvt.u32.u64 %0, t; }"
        : "=r"(a) : "l"(p));
    return a;
}

__device__ __forceinline__ void ldmat4(uint32_t* r, uint32_t addr) {
    asm volatile("ldmatrix.sync.aligned.m8n8.x4.shared.b16 {%0,%1,%2,%3}, [%4];"
                 : "=r"(r[0]), "=r"(r[1]), "=r"(r[2]), "=r"(r[3]) : "r"(addr));
}

__device__ __forceinline__ void mma16816(float* d, const uint32_t* a, uint32_t b0, uint32_t b1) {
    asm volatile("mma.sync.aligned.m16n8k16.row.col.f32.f16.f16.f32 "
                 "{%0,%1,%2,%3}, {%4,%5,%6,%7}, {%8,%9}, {%0,%1,%2,%3};"
                 : "+f"(d[0]), "+f"(d[1]), "+f"(d[2]), "+f"(d[3])
                 : "r"(a[0]), "r"(a[1]), "r"(a[2]), "r"(a[3]), "r"(b0), "r"(b1));
}

__device__ __forceinline__ void cp_async16(uint32_t saddr, const void* gaddr) {
    asm volatile("cp.async.ca.shared.global [%0], [%1], 16;"
                 :: "r"(saddr), "l"(gaddr));
}
#define CP_ASYNC_COMMIT() asm volatile("cp.async.commit_group;" ::: "memory")
#define CP_ASYNC_WAIT0()  asm volatile("cp.async.wait_group 0;"  ::: "memory")

// accurate fast tanh (MUFU ex2 + fast div), rel err ~1e-7
__device__ __forceinline__ float tanh_acc(float x) {
    float ax = fabsf(x);
    float t  = __expf(-2.f * ax);
    float r  = __fdividef(1.f - t, 1.f + t);
    return copysignf(r, x);
}

// ===========================================================================
// Scratch
// ===========================================================================
__device__ float g_qproj[Bsz * Hsz];
__device__ float g_ctx[Bsz * Dsz];
__device__ float g_x0[Bsz * (Esz + Dsz)];
__device__ float g_gi[Bsz * 3 * Hsz];
__device__ float g_gh[Bsz * 3 * Hsz];
__device__ __half g_wkH[Hsz * Dsz];     // Wk fp16

// ---------------------------------------------------------------------------
__global__ void wk_split_kernel(const float* __restrict__ wk) {
    int i = blockIdx.x * blockDim.x + threadIdx.x;
    if (i < Hsz * Dsz) g_wkH[i] = __float2half_rn(wk[i]);
}

// ---------------------------------------------------------------------------
// Generic tiled fp32 GEMM: C[m,n] = sum_k A[m,k] * W[n,k] (+ bias[n])
// ---------------------------------------------------------------------------
__global__ __launch_bounds__(256) void gemm_bias_kernel(
    const float* __restrict__ A, const float* __restrict__ W,
    const float* __restrict__ bias, float* __restrict__ C, int N, int K)
{
    __shared__ float As[16][64];
    __shared__ float Ws[16][64];
    int t  = threadIdx.x;
    int m0 = blockIdx.y * 64;
    int n0 = blockIdx.x * 64;
    int tx = t & 15, ty = t >> 4;
    int lm = t >> 2, kv = t & 3;

    float acc[4][4] = {};
    for (int k0 = 0; k0 < K; k0 += 16) {
        float4 avv = *(const float4*)(A + (size_t)(m0 + lm) * K + k0 + kv * 4);
        As[kv*4+0][lm] = avv.x; As[kv*4+1][lm] = avv.y;
        As[kv*4+2][lm] = avv.z; As[kv*4+3][lm] = avv.w;
        float4 wv = make_float4(0.f, 0.f, 0.f, 0.f);
        if (n0 + lm < N)
            wv = *(const float4*)(W + (size_t)(n0 + lm) * K + k0 + kv * 4);
        Ws[kv*4+0][lm] = wv.x; Ws[kv*4+1][lm] = wv.y;
        Ws[kv*4+2][lm] = wv.z; Ws[kv*4+3][lm] = wv.w;
        __syncthreads();
        #pragma unroll
        for (int kk = 0; kk < 16; kk++) {
            float a[4];
            #pragma unroll
            for (int j = 0; j < 4; j++) a[j] = As[kk][ty * 4 + j];
            float4 bv = *(const float4*)&Ws[kk][tx * 4];
            #pragma unroll
            for (int j = 0; j < 4; j++) {
                acc[j][0] += a[j] * bv.x; acc[j][1] += a[j] * bv.y;
                acc[j][2] += a[j] * bv.z; acc[j][3] += a[j] * bv.w;
            }
        }
        __syncthreads();
    }
    #pragma unroll
    for (int j = 0; j < 4; j++) {
        int m = m0 + ty * 4 + j;
        #pragma unroll
        for (int i = 0; i < 4; i++) {
            int n = n0 + tx * 4 + i;
            if (n < N) {
                float v = acc[j][i];
                if (bias) v += bias[n];
                C[(size_t)m * N + n] = v;
            }
        }
    }
}

// ===========================================================================
// FUSED scores + softmax + context. One block per batch row.
// 8 tiles of 64 l-rows; per tile: enc -> fp16 smem (full K=256), HMMA scores,
// flash-style online softmax, ctx accumulated from the resident fp16 tile.
// Warps: 8 as 2(row, 32l) x 4(col, 32h). Smem rows 512B, XOR-16B swizzle.
// ===========================================================================
#define SB_OFF 0                 // Wk fp16 resident: 128 rows x 512B = 64KB
#define SA_OFF 65536             // enc tile fp16:     64 rows x 512B = 32KB
#define FS_SMEM (65536 + 32768)

__global__ __launch_bounds__(256, 2) void fused_attn_kernel(
    const float* __restrict__ enc, const float* __restrict__ attn_v,
    float* __restrict__ attnw_out, float* __restrict__ ctx_out)
{
    extern __shared__ char smem[];
    __shared__ float qs[128], vs[128];
    __shared__ float sred[4][64];
    __shared__ float s_all[Lsz];
    __shared__ float e_w[64];
    __shared__ float red2[2];
    __shared__ float sm_m, sm_Z, sm_scale;

    uint32_t sbase = smem_to_u32(smem);
    int t    = threadIdx.x;
    int lane = t & 31, w = t >> 5;
    int wr   = w & 1,  wc = w >> 1;
    int b    = blockIdx.x;

    // ---- preload all of Wk fp16 (64KB), 512B rows, XOR swizzle ----
    #pragma unroll
    for (int i = 0; i < 16; i++) {
        int u   = t + i * 256;          // 16B units, 32 per row
        int row = u >> 5;
        int cu  = u & 31;
        uint32_t dst = sbase + SB_OFF + (uint32_t)(row * 512 + ((cu ^ (row & 7)) << 4));
        cp_async16(dst, g_wkH + (size_t)row * Dsz + cu * 8);
    }
    CP_ASYNC_COMMIT();

    if (t < 128) { qs[t] = g_qproj[b * Hsz + t]; vs[t] = attn_v[t]; }
    if (t == 0)  { sm_m = -1e30f; sm_Z = 0.f; }

    const float* encb = enc + (size_t)b * Lsz * Dsz;
    float ctx = 0.f;                     // thread t owns d = t

    for (int tile = 0; tile < 8; tile++) {
        int l0 = tile * 64;
        // ---- stage enc tile: 64 rows x 256 d -> fp16, swizzled ----
        #pragma unroll
        for (int i = 0; i < 8; i++) {
            int u   = t + i * 256;      // unit = (row, cu), 32 units/row
            int row = u >> 5;
            int cu  = u & 31;
            const float* src = encb + (size_t)(l0 + row) * Dsz + cu * 8;
            float4 v0 = *(const float4*)(src);
            float4 v1 = *(const float4*)(src + 4);
            __half2 h0 = __floats2half2_rn(v0.x, v0.y);
            __half2 h1 = __floats2half2_rn(v0.z, v0.w);
            __half2 h2 = __floats2half2_rn(v1.x, v1.y);
            __half2 h3 = __floats2half2_rn(v1.z, v1.w);
            uint4 pk;
            pk.x = *(uint32_t*)&h0; pk.y = *(uint32_t*)&h1;
            pk.z = *(uint32_t*)&h2; pk.w = *(uint32_t*)&h3;
            uint32_t off = (uint32_t)(row * 512 + ((cu ^ (row & 7)) << 4));
            *(uint4*)(smem + SA_OFF + off) = pk;
        }
        if (tile == 0) CP_ASYNC_WAIT0();
        __syncthreads();

        // ---- MMA: 64l x 128h, K=256 (16 k-steps) ----
        float acc[2][4][4];
        #pragma unroll
        for (int mt = 0; mt < 2; mt++)
            #pragma unroll
            for (int nt = 0; nt < 4; nt++)
                #pragma unroll
                for (int i = 0; i < 4; i++) acc[mt][nt][i] = 0.f;

        #pragma unroll
        for (int ks = 0; ks < 16; ks++) {
            int cuk = ks * 2 + (lane >> 4);
            uint32_t ah[2][4];
            #pragma unroll
            for (int mt = 0; mt < 2; mt++) {
                int row = wr * 32 + mt * 16 + (lane & 15);
                uint32_t off = (uint32_t)(row * 512 + ((cuk ^ (row & 7)) << 4));
                ldmat4(ah[mt], sbase + SA_OFF + off);
            }
            #pragma unroll
            for (int p = 0; p < 2; p++) {
                int row = wc * 32 + p * 16 + (lane & 15);
                uint32_t off = (uint32_t)(row * 512 + ((cuk ^ (row & 7)) << 4));
                uint32_t rb[4];
                ldmat4(rb, sbase + SB_OFF + off);
                #pragma unroll
                for (int mt = 0; mt < 2; mt++) {
                    mma16816(acc[mt][p*2],   ah[mt], rb[0], rb[2]);
                    mma16816(acc[mt][p*2+1], ah[mt], rb[1], rb[3]);
                }
            }
        }

        // ---- scores epilogue: s[l] = sum_h v[h]*tanh(acc + qproj[h]) ----
        float part[4];
        #pragma unroll
        for (int mt = 0; mt < 2; mt++)
            #pragma unroll
            for (int half = 0; half < 2; half++) {
                float p = 0.f;
                #pragma unroll
                for (int nt = 0; nt < 4; nt++)
                    #pragma unroll
                    for (int j = 0; j < 2; j++) {
                        int h = wc * 32 + nt * 8 + (lane & 3) * 2 + j;
                        float e = acc[mt][nt][half * 2 + j] + qs[h];
                        p += vs[h] * tanh_acc(e);
                    }
                part[mt * 2 + half] = p;
            }
        #pragma unroll
        for (int k = 0; k < 4; k++) {
            part[k] += __shfl_xor_sync(0xffffffffu, part[k], 1);
            part[k] += __shfl_xor_sync(0xffffffffu, part[k], 2);
        }
        if ((lane & 3) == 0) {
            #pragma unroll
            for (int mt = 0; mt < 2; mt++)
                #pragma unroll
                for (int half = 0; half < 2; half++) {
                    int row = wr * 32 + mt * 16 + half * 8 + (lane >> 2);
                    sred[wc][row] = part[mt * 2 + half];
                }
        }
        __syncthreads();

        // ---- flash update: m, Z, e_w (threads 0..63) ----
        float s = 0.f;
        if (t < 64) {
            s = sred[0][t] + sred[1][t] + sred[2][t] + sred[3][t];
            s_all[l0 + t] = s;
            float mx = s;
            #pragma unroll
            for (int o = 16; o > 0; o >>= 1)
                mx = fmaxf(mx, __shfl_xor_sync(0xffffffffu, mx, o));
            if (lane == 0) red2[t >> 5] = mx;
        }
        __syncthreads();
        if (t == 0) {
            float m_new = fmaxf(sm_m, fmaxf(red2[0], red2[1]));
            sm_scale = __expf(sm_m - m_new);
            sm_m = m_new;
        }
        __syncthreads();
        if (t < 64) {
            float e = __expf(s - sm_m);
            e_w[t] = e;
            #pragma unroll
            for (int o = 16; o > 0; o >>= 1)
                e += __shfl_xor_sync(0xffffffffu, e, o);
            if (lane == 0) red2[t >> 5] = e;
        }
        __syncthreads();
        if (t == 0) sm_Z = sm_Z * sm_scale + red2[0] + red2[1];

        // ---- ctx accumulate from resident fp16 tile: thread t owns d=t ----
        {
            float cacc = 0.f;
            int cu = t >> 3, byo = (t & 7) * 2;
            #pragma unroll 8
            for (int l = 0; l < 64; l++) {
                uint32_t off = (uint32_t)(l * 512 + ((cu ^ (l & 7)) << 4) + byo);
                float ev = *(const __half*)(smem + SA_OFF + off);
                cacc += e_w[l] * ev;
            }
            ctx = ctx * sm_scale + cacc;
        }
        __syncthreads();   // protect SA + e_w before next tile overwrites
    }

    // ---- finalize ----
    float invZ = 1.f / sm_Z;
    ctx_out[(size_t)b * Dsz + t] = ctx * invZ;
    float m = sm_m;
    attnw_out[(size_t)b * Lsz + t]       = __expf(s_all[t]       - m) * invZ;
    attnw_out[(size_t)b * Lsz + t + 256] = __expf(s_all[t + 256] - m) * invZ;
}

// ---------------------------------------------------------------------------
__global__ void concat_kernel(const float* __restrict__ embed) {
    int i = blockIdx.x * blockDim.x + threadIdx.x;
    if (i >= Bsz * (Esz + Dsz)) return;
    int b = i / (Esz + Dsz), c = i - b * (Esz + Dsz);
    g_x0[i] = (c < Esz) ? embed[b * Esz + c] : g_ctx[b * Dsz + (c - Esz)];
}

__global__ void gru_kernel(const float* __restrict__ hprev, float* __restrict__ hnew) {
    int b = blockIdx.x, h = threadIdx.x;
    int base = b * 3 * Hsz;
    float r = 1.f / (1.f + __expf(-(g_gi[base + h]       + g_gh[base + h])));
    float z = 1.f / (1.f + __expf(-(g_gi[base + Hsz + h] + g_gh[base + Hsz + h])));
    float n = tanhf(g_gi[base + 2 * Hsz + h] + r * g_gh[base + 2 * Hsz + h]);
    hnew[b * Hsz + h] = (1.f - z) * n + z * hprev[b * Hsz + h];
}

// ===========================================================================
extern "C" void kernel_launch(void* const* d_in, const int* in_sizes, int n_in,
                              void* d_out, int out_size)
{
    const float* embed  = (const float*)d_in[0];
    const float* hidden = (const float*)d_in[1];
    const float* enc    = (const float*)d_in[2];
    const float* Wq     = (const float*)d_in[3];
    const float* Wk     = (const float*)d_in[4];
    const float* av     = (const float*)d_in[5];
    const float* Wih0   = (const float*)d_in[6];
    const float* Whh0   = (const float*)d_in[7];
    const float* bih0   = (const float*)d_in[8];
    const float* bhh0   = (const float*)d_in[9];
    const float* Wih1   = (const float*)d_in[10];
    const float* Whh1   = (const float*)d_in[11];
    const float* bih1   = (const float*)d_in[12];
    const float* bhh1   = (const float*)d_in[13];
    const float* Wout   = (const float*)d_in[14];
    const float* bout   = (const float*)d_in[15];

    float* out_logits = (float*)d_out;
    float* out_hidden = out_logits + (size_t)Bsz * Vsz;
    float* out_attnw  = out_hidden + (size_t)2 * Bsz * Hsz;

    float *p_qproj, *p_ctx, *p_x0, *p_gi, *p_gh;
    cudaGetSymbolAddress((void**)&p_qproj, g_qproj);
    cudaGetSymbolAddress((void**)&p_ctx,   g_ctx);
    cudaGetSymbolAddress((void**)&p_x0,    g_x0);
    cudaGetSymbolAddress((void**)&p_gi,    g_gi);
    cudaGetSymbolAddress((void**)&p_gh,    g_gh);

    cudaFuncSetAttribute(fused_attn_kernel,
                         cudaFuncAttributeMaxDynamicSharedMemorySize, FS_SMEM);

    const float* h0_prev = hidden;
    const float* h1_prev = hidden + (size_t)Bsz * Hsz;

    // 1) Wk fp16 + query projection
    wk_split_kernel<<<(Hsz * Dsz + 255) / 256, 256>>>(Wk);
    gemm_bias_kernel<<<dim3(Hsz / 64, Bsz / 64), 256>>>(
        h1_prev, Wq, nullptr, p_qproj, Hsz, Hsz);

    // 2) fused attention: scores + softmax + context, enc read once
    fused_attn_kernel<<<Bsz, 256, FS_SMEM>>>(enc, av, out_attnw, p_ctx);

    // 3) GRU layer 0
    concat_kernel<<<(Bsz * (Esz + Dsz) + 255) / 256, 256>>>(embed);
    gemm_bias_kernel<<<dim3(384 / 64, Bsz / 64), 256>>>(
        p_x0, Wih0, bih0, p_gi, 3 * Hsz, Esz + Dsz);
    gemm_bias_kernel<<<dim3(384 / 64, Bsz / 64), 256>>>(
        h0_prev, Whh0, bhh0, p_gh, 3 * Hsz, Hsz);
    gru_kernel<<<Bsz, Hsz>>>(h0_prev, out_hidden);

    // 4) GRU layer 1
    gemm_bias_kernel<<<dim3(384 / 64, Bsz / 64), 256>>>(
        out_hidden, Wih1, bih1, p_gi, 3 * Hsz, Hsz);
    gemm_bias_kernel<<<dim3(384 / 64, Bsz / 64), 256>>>(
        h1_prev, Whh1, bhh1, p_gh, 3 * Hsz, Hsz);
    gru_kernel<<<Bsz, Hsz>>>(h1_prev, out_hidden + (size_t)Bsz * Hsz);

    // 5) output projection
    gemm_bias_kernel<<<dim3((Vsz + 63) / 64, Bsz / 64), 256>>>(
        out_hidden + (size_t)Bsz * Hsz, Wout, bout, out_logits, Vsz, Hsz);
}

// round 9
// speedup vs baseline: 3.5030x; 1.0333x over previous
#include <cuda_runtime.h>
#include <cuda_bf16.h>
#include <cuda_fp16.h>
#include <cstdint>

#define Bsz 2048
#define Lsz 512
#define Esz 64
#define Hsz 128
#define Dsz 256
#define Vsz 1000

__device__ __forceinline__ uint32_t smem_to_u32(const void* p) {
    uint32_t a;
    asm("{ .reg .u64 t; cvta.to.shared.u64 t, %1; cvt.u32.u64 %0, t; }"
        : "=r"(a) : "l"(p));
    return a;
}

__device__ __forceinline__ void ldmat4(uint32_t* r, uint32_t addr) {
    asm volatile("ldmatrix.sync.aligned.m8n8.x4.shared.b16 {%0,%1,%2,%3}, [%4];"
                 : "=r"(r[0]), "=r"(r[1]), "=r"(r[2]), "=r"(r[3]) : "r"(addr));
}

__device__ __forceinline__ void mma16816(float* d, const uint32_t* a, uint32_t b0, uint32_t b1) {
    asm volatile("mma.sync.aligned.m16n8k16.row.col.f32.f16.f16.f32 "
                 "{%0,%1,%2,%3}, {%4,%5,%6,%7}, {%8,%9}, {%0,%1,%2,%3};"
                 : "+f"(d[0]), "+f"(d[1]), "+f"(d[2]), "+f"(d[3])
                 : "r"(a[0]), "r"(a[1]), "r"(a[2]), "r"(a[3]), "r"(b0), "r"(b1));
}

__device__ __forceinline__ void cp_async16(uint32_t saddr, const void* gaddr) {
    asm volatile("cp.async.ca.shared.global [%0], [%1], 16;"
                 :: "r"(saddr), "l"(gaddr));
}
#define CP_ASYNC_COMMIT() asm volatile("cp.async.commit_group;" ::: "memory")
#define CP_ASYNC_WAIT0()  asm volatile("cp.async.wait_group 0;"  ::: "memory")

// accurate fast tanh (MUFU ex2 + fast div), rel err ~1e-7
__device__ __forceinline__ float tanh_acc(float x) {
    float ax = fabsf(x);
    float t  = __expf(-2.f * ax);
    float r  = __fdividef(1.f - t, 1.f + t);
    return copysignf(r, x);
}

// ===========================================================================
// Scratch
// ===========================================================================
__device__ float g_qproj[Bsz * Hsz];
__device__ float g_ctx[Bsz * Dsz];
__device__ float g_x0[Bsz * (Esz + Dsz)];
__device__ float g_gi[Bsz * 3 * Hsz];
__device__ float g_gh[Bsz * 3 * Hsz];
__device__ __half g_wkH[Hsz * Dsz];     // Wk fp16

// ---------------------------------------------------------------------------
__global__ void wk_split_kernel(const float* __restrict__ wk) {
    int i = blockIdx.x * blockDim.x + threadIdx.x;
    if (i < Hsz * Dsz) g_wkH[i] = __float2half_rn(wk[i]);
}

// ---------------------------------------------------------------------------
// Generic tiled fp32 GEMM: C[m,n] = sum_k A[m,k] * W[n,k] (+ bias[n])
// ---------------------------------------------------------------------------
__global__ __launch_bounds__(256) void gemm_bias_kernel(
    const float* __restrict__ A, const float* __restrict__ W,
    const float* __restrict__ bias, float* __restrict__ C, int N, int K)
{
    __shared__ float As[16][64];
    __shared__ float Ws[16][64];
    int t  = threadIdx.x;
    int m0 = blockIdx.y * 64;
    int n0 = blockIdx.x * 64;
    int tx = t & 15, ty = t >> 4;
    int lm = t >> 2, kv = t & 3;

    float acc[4][4] = {};
    for (int k0 = 0; k0 < K; k0 += 16) {
        float4 avv = *(const float4*)(A + (size_t)(m0 + lm) * K + k0 + kv * 4);
        As[kv*4+0][lm] = avv.x; As[kv*4+1][lm] = avv.y;
        As[kv*4+2][lm] = avv.z; As[kv*4+3][lm] = avv.w;
        float4 wv = make_float4(0.f, 0.f, 0.f, 0.f);
        if (n0 + lm < N)
            wv = *(const float4*)(W + (size_t)(n0 + lm) * K + k0 + kv * 4);
        Ws[kv*4+0][lm] = wv.x; Ws[kv*4+1][lm] = wv.y;
        Ws[kv*4+2][lm] = wv.z; Ws[kv*4+3][lm] = wv.w;
        __syncthreads();
        #pragma unroll
        for (int kk = 0; kk < 16; kk++) {
            float a[4];
            #pragma unroll
            for (int j = 0; j < 4; j++) a[j] = As[kk][ty * 4 + j];
            float4 bv = *(const float4*)&Ws[kk][tx * 4];
            #pragma unroll
            for (int j = 0; j < 4; j++) {
                acc[j][0] += a[j] * bv.x; acc[j][1] += a[j] * bv.y;
                acc[j][2] += a[j] * bv.z; acc[j][3] += a[j] * bv.w;
            }
        }
        __syncthreads();
    }
    #pragma unroll
    for (int j = 0; j < 4; j++) {
        int m = m0 + ty * 4 + j;
        #pragma unroll
        for (int i = 0; i < 4; i++) {
            int n = n0 + tx * 4 + i;
            if (n < N) {
                float v = acc[j][i];
                if (bias) v += bias[n];
                C[(size_t)m * N + n] = v;
            }
        }
    }
}

// ===========================================================================
// FUSED scores + softmax + context. One block per batch row.
// Fixed-max softmax (scores bounded by ||v||_1 ~ 5): no max tracking,
// no rescale, per-thread Z partials. Register prefetch of next tile (half).
// ===========================================================================
#define SB_OFF 0                 // Wk fp16 resident: 128 rows x 512B = 64KB
#define SA_OFF 65536             // enc tile fp16:     64 rows x 512B = 32KB
#define FS_SMEM (65536 + 32768)

__global__ __launch_bounds__(256, 2) void fused_attn_kernel(
    const float* __restrict__ enc, const float* __restrict__ attn_v,
    float* __restrict__ attnw_out, float* __restrict__ ctx_out)
{
    extern __shared__ char smem[];
    __shared__ float qs[128], vs[128];
    __shared__ float sred[4][64];
    __shared__ float e_all[Lsz];
    __shared__ float e_w[64];
    __shared__ float zred[2];
    __shared__ float sm_invZ;

    uint32_t sbase = smem_to_u32(smem);
    int t    = threadIdx.x;
    int lane = t & 31, w = t >> 5;
    int wr   = w & 1,  wc = w >> 1;
    int b    = blockIdx.x;

    // ---- preload all of Wk fp16 (64KB), 512B rows, XOR swizzle ----
    #pragma unroll
    for (int i = 0; i < 16; i++) {
        int u   = t + i * 256;
        int row = u >> 5;
        int cu  = u & 31;
        uint32_t dst = sbase + SB_OFF + (uint32_t)(row * 512 + ((cu ^ (row & 7)) << 4));
        cp_async16(dst, g_wkH + (size_t)row * Dsz + cu * 8);
    }
    CP_ASYNC_COMMIT();

    if (t < 128) { qs[t] = g_qproj[b * Hsz + t]; vs[t] = attn_v[t]; }

    const float* encb = enc + (size_t)b * Lsz * Dsz;
    float2 ctx = make_float2(0.f, 0.f);   // t<128 owns d = 2t, 2t+1
    float Zloc = 0.f;                      // t<64 partial

    // unit decomposition for staging: u = t + i*256, row = u>>5, cu = u&31
    int s_row = t >> 5;          // base row for i-th unit: row = s_row + i*8
    int s_cu  = t & 31;

    // ---- prefetch tile 0, first half (units i=0..3) ----
    float4 pf[8];
    #pragma unroll
    for (int i = 0; i < 4; i++) {
        const float* src = encb + (size_t)(s_row + i * 8) * Dsz + s_cu * 8;
        pf[i * 2]     = *(const float4*)(src);
        pf[i * 2 + 1] = *(const float4*)(src + 4);
    }

    for (int tile = 0; tile < 8; tile++) {
        int l0 = tile * 64;
        // ---- stage: prefetched half ----
        #pragma unroll
        for (int i = 0; i < 4; i++) {
            int row = s_row + i * 8;
            __half2 h0 = __floats2half2_rn(pf[i*2].x,   pf[i*2].y);
            __half2 h1 = __floats2half2_rn(pf[i*2].z,   pf[i*2].w);
            __half2 h2 = __floats2half2_rn(pf[i*2+1].x, pf[i*2+1].y);
            __half2 h3 = __floats2half2_rn(pf[i*2+1].z, pf[i*2+1].w);
            uint4 pk;
            pk.x = *(uint32_t*)&h0; pk.y = *(uint32_t*)&h1;
            pk.z = *(uint32_t*)&h2; pk.w = *(uint32_t*)&h3;
            uint32_t off = (uint32_t)(row * 512 + ((s_cu ^ (row & 7)) << 4));
            *(uint4*)(smem + SA_OFF + off) = pk;
        }
        // ---- stage: synchronous half (units i=4..7) ----
        #pragma unroll
        for (int i = 4; i < 8; i++) {
            int row = s_row + i * 8;
            const float* src = encb + (size_t)(l0 + row) * Dsz + s_cu * 8;
            float4 v0 = *(const float4*)(src);
            float4 v1 = *(const float4*)(src + 4);
            __half2 h0 = __floats2half2_rn(v0.x, v0.y);
            __half2 h1 = __floats2half2_rn(v0.z, v0.w);
            __half2 h2 = __floats2half2_rn(v1.x, v1.y);
            __half2 h3 = __floats2half2_rn(v1.z, v1.w);
            uint4 pk;
            pk.x = *(uint32_t*)&h0; pk.y = *(uint32_t*)&h1;
            pk.z = *(uint32_t*)&h2; pk.w = *(uint32_t*)&h3;
            uint32_t off = (uint32_t)(row * 512 + ((s_cu ^ (row & 7)) << 4));
            *(uint4*)(smem + SA_OFF + off) = pk;
        }
        if (tile == 0) CP_ASYNC_WAIT0();
        __syncthreads();

        // ---- issue prefetch for next tile (overlaps MMA/epilogue/ctx) ----
        if (tile < 7) {
            const float* nb = encb + (size_t)(l0 + 64) * Dsz;
            #pragma unroll
            for (int i = 0; i < 4; i++) {
                const float* src = nb + (size_t)(s_row + i * 8) * Dsz + s_cu * 8;
                pf[i * 2]     = *(const float4*)(src);
                pf[i * 2 + 1] = *(const float4*)(src + 4);
            }
        }

        // ---- MMA: 64l x 128h, K=256 (16 k-steps) ----
        float acc[2][4][4];
        #pragma unroll
        for (int mt = 0; mt < 2; mt++)
            #pragma unroll
            for (int nt = 0; nt < 4; nt++)
                #pragma unroll
                for (int i = 0; i < 4; i++) acc[mt][nt][i] = 0.f;

        #pragma unroll
        for (int ks = 0; ks < 16; ks++) {
            int cuk = ks * 2 + (lane >> 4);
            uint32_t ah[2][4];
            #pragma unroll
            for (int mt = 0; mt < 2; mt++) {
                int row = wr * 32 + mt * 16 + (lane & 15);
                uint32_t off = (uint32_t)(row * 512 + ((cuk ^ (row & 7)) << 4));
                ldmat4(ah[mt], sbase + SA_OFF + off);
            }
            #pragma unroll
            for (int p = 0; p < 2; p++) {
                int row = wc * 32 + p * 16 + (lane & 15);
                uint32_t off = (uint32_t)(row * 512 + ((cuk ^ (row & 7)) << 4));
                uint32_t rb[4];
                ldmat4(rb, sbase + SB_OFF + off);
                #pragma unroll
                for (int mt = 0; mt < 2; mt++) {
                    mma16816(acc[mt][p*2],   ah[mt], rb[0], rb[2]);
                    mma16816(acc[mt][p*2+1], ah[mt], rb[1], rb[3]);
                }
            }
        }

        // ---- scores epilogue ----
        float part[4];
        #pragma unroll
        for (int mt = 0; mt < 2; mt++)
            #pragma unroll
            for (int half = 0; half < 2; half++) {
                float p = 0.f;
                #pragma unroll
                for (int nt = 0; nt < 4; nt++)
                    #pragma unroll
                    for (int j = 0; j < 2; j++) {
                        int h = wc * 32 + nt * 8 + (lane & 3) * 2 + j;
                        float e = acc[mt][nt][half * 2 + j] + qs[h];
                        p += vs[h] * tanh_acc(e);
                    }
                part[mt * 2 + half] = p;
            }
        #pragma unroll
        for (int k = 0; k < 4; k++) {
            part[k] += __shfl_xor_sync(0xffffffffu, part[k], 1);
            part[k] += __shfl_xor_sync(0xffffffffu, part[k], 2);
        }
        if ((lane & 3) == 0) {
            #pragma unroll
            for (int mt = 0; mt < 2; mt++)
                #pragma unroll
                for (int half = 0; half < 2; half++) {
                    int row = wr * 32 + mt * 16 + half * 8 + (lane >> 2);
                    sred[wc][row] = part[mt * 2 + half];
                }
        }
        __syncthreads();

        // ---- fixed-max softmax: e = exp(s), Z partial per thread ----
        if (t < 64) {
            float s = sred[0][t] + sred[1][t] + sred[2][t] + sred[3][t];
            float e = __expf(s);
            e_w[t] = e;
            e_all[l0 + t] = e;
            Zloc += e;
        }
        __syncthreads();

        // ---- ctx accumulate (t<128, half2 per step) ----
        if (t < 128) {
            int cu = t >> 2, byo = (4 * t) & 15;
            float2 cacc = make_float2(0.f, 0.f);
            #pragma unroll 8
            for (int l = 0; l < 64; l++) {
                uint32_t off = (uint32_t)(l * 512 + ((cu ^ (l & 7)) << 4) + byo);
                __half2 hv = *(const __half2*)(smem + SA_OFF + off);
                float2 fv = __half22float2(hv);
                float e = e_w[l];
                cacc.x += e * fv.x;
                cacc.y += e * fv.y;
            }
            ctx.x += cacc.x;
            ctx.y += cacc.y;
        }
        __syncthreads();   // protect SA + e_w before next tile overwrites
    }

    // ---- Z reduction (t<64 hold partials) ----
    if (t < 64) {
        float z = Zloc;
        #pragma unroll
        for (int o = 16; o > 0; o >>= 1)
            z += __shfl_xor_sync(0xffffffffu, z, o);
        if (lane == 0) zred[t >> 5] = z;
    }
    __syncthreads();
    if (t == 0) sm_invZ = 1.f / (zred[0] + zred[1]);
    __syncthreads();

    float invZ = sm_invZ;
    if (t < 128) {
        ctx_out[(size_t)b * Dsz + 2 * t]     = ctx.x * invZ;
        ctx_out[(size_t)b * Dsz + 2 * t + 1] = ctx.y * invZ;
    }
    attnw_out[(size_t)b * Lsz + t]       = e_all[t]       * invZ;
    attnw_out[(size_t)b * Lsz + t + 256] = e_all[t + 256] * invZ;
}

// ---------------------------------------------------------------------------
__global__ void concat_kernel(const float* __restrict__ embed) {
    int i = blockIdx.x * blockDim.x + threadIdx.x;
    if (i >= Bsz * (Esz + Dsz)) return;
    int b = i / (Esz + Dsz), c = i - b * (Esz + Dsz);
    g_x0[i] = (c < Esz) ? embed[b * Esz + c] : g_ctx[b * Dsz + (c - Esz)];
}

__global__ void gru_kernel(const float* __restrict__ hprev, float* __restrict__ hnew) {
    int b = blockIdx.x, h = threadIdx.x;
    int base = b * 3 * Hsz;
    float r = 1.f / (1.f + __expf(-(g_gi[base + h]       + g_gh[base + h])));
    float z = 1.f / (1.f + __expf(-(g_gi[base + Hsz + h] + g_gh[base + Hsz + h])));
    float n = tanhf(g_gi[base + 2 * Hsz + h] + r * g_gh[base + 2 * Hsz + h]);
    hnew[b * Hsz + h] = (1.f - z) * n + z * hprev[b * Hsz + h];
}

// ===========================================================================
extern "C" void kernel_launch(void* const* d_in, const int* in_sizes, int n_in,
                              void* d_out, int out_size)
{
    const float* embed  = (const float*)d_in[0];
    const float* hidden = (const float*)d_in[1];
    const float* enc    = (const float*)d_in[2];
    const float* Wq     = (const float*)d_in[3];
    const float* Wk     = (const float*)d_in[4];
    const float* av     = (const float*)d_in[5];
    const float* Wih0   = (const float*)d_in[6];
    const float* Whh0   = (const float*)d_in[7];
    const float* bih0   = (const float*)d_in[8];
    const float* bhh0   = (const float*)d_in[9];
    const float* Wih1   = (const float*)d_in[10];
    const float* Whh1   = (const float*)d_in[11];
    const float* bih1   = (const float*)d_in[12];
    const float* bhh1   = (const float*)d_in[13];
    const float* Wout   = (const float*)d_in[14];
    const float* bout   = (const float*)d_in[15];

    float* out_logits = (float*)d_out;
    float* out_hidden = out_logits + (size_t)Bsz * Vsz;
    float* out_attnw  = out_hidden + (size_t)2 * Bsz * Hsz;

    float *p_qproj, *p_ctx, *p_x0, *p_gi, *p_gh;
    cudaGetSymbolAddress((void**)&p_qproj, g_qproj);
    cudaGetSymbolAddress((void**)&p_ctx,   g_ctx);
    cudaGetSymbolAddress((void**)&p_x0,    g_x0);
    cudaGetSymbolAddress((void**)&p_gi,    g_gi);
    cudaGetSymbolAddress((void**)&p_gh,    g_gh);

    cudaFuncSetAttribute(fused_attn_kernel,
                         cudaFuncAttributeMaxDynamicSharedMemorySize, FS_SMEM);

    const float* h0_prev = hidden;
    const float* h1_prev = hidden + (size_t)Bsz * Hsz;

    // 1) Wk fp16 + query projection
    wk_split_kernel<<<(Hsz * Dsz + 255) / 256, 256>>>(Wk);
    gemm_bias_kernel<<<dim3(Hsz / 64, Bsz / 64), 256>>>(
        h1_prev, Wq, nullptr, p_qproj, Hsz, Hsz);

    // 2) fused attention: scores + softmax + context, enc read once
    fused_attn_kernel<<<Bsz, 256, FS_SMEM>>>(enc, av, out_attnw, p_ctx);

    // 3) GRU layer 0
    concat_kernel<<<(Bsz * (Esz + Dsz) + 255) / 256, 256>>>(embed);
    gemm_bias_kernel<<<dim3(384 / 64, Bsz / 64), 256>>>(
        p_x0, Wih0, bih0, p_gi, 3 * Hsz, Esz + Dsz);
    gemm_bias_kernel<<<dim3(384 / 64, Bsz / 64), 256>>>(
        h0_prev, Whh0, bhh0, p_gh, 3 * Hsz, Hsz);
    gru_kernel<<<Bsz, Hsz>>>(h0_prev, out_hidden);

    // 4) GRU layer 1
    gemm_bias_kernel<<<dim3(384 / 64, Bsz / 64), 256>>>(
        out_hidden, Wih1, bih1, p_gi, 3 * Hsz, Hsz);
    gemm_bias_kernel<<<dim3(384 / 64, Bsz / 64), 256>>>(
        h1_prev, Whh1, bhh1, p_gh, 3 * Hsz, Hsz);
    gru_kernel<<<Bsz, Hsz>>>(h1_prev, out_hidden + (size_t)Bsz * Hsz);

    // 5) output projection
    gemm_bias_kernel<<<dim3((Vsz + 63) / 64, Bsz / 64), 256>>>(
        out_hidden + (size_t)Bsz * Hsz, Wout, bout, out_logits, Vsz, Hsz);
}

// round 10
// speedup vs baseline: 3.5911x; 1.0251x over previous
#include <cuda_runtime.h>
#include <cuda_bf16.h>
#include <cuda_fp16.h>
#include <cstdint>

#define Bsz 2048
#define Lsz 512
#define Esz 64
#define Hsz 128
#define Dsz 256
#define Vsz 1000
#define X0W 320                      // E + D

#define SMEM_SWIZZLE_128B(off) ((off) ^ (((off) >> 3) & 0x70))

__device__ __forceinline__ uint32_t smem_to_u32(const void* p) {
    uint32_t a;
    asm("{ .reg .u64 t; cvta.to.shared.u64 t, %1; cvt.u32.u64 %0, t; }"
        : "=r"(a) : "l"(p));
    return a;
}
__device__ __forceinline__ void ldmat4(uint32_t* r, uint32_t addr) {
    asm volatile("ldmatrix.sync.aligned.m8n8.x4.shared.b16 {%0,%1,%2,%3}, [%4];"
                 : "=r"(r[0]), "=r"(r[1]), "=r"(r[2]), "=r"(r[3]) : "r"(addr));
}
__device__ __forceinline__ void mma_f16(float* d, const uint32_t* a, uint32_t b0, uint32_t b1) {
    asm volatile("mma.sync.aligned.m16n8k16.row.col.f32.f16.f16.f32 "
                 "{%0,%1,%2,%3}, {%4,%5,%6,%7}, {%8,%9}, {%0,%1,%2,%3};"
                 : "+f"(d[0]), "+f"(d[1]), "+f"(d[2]), "+f"(d[3])
                 : "r"(a[0]), "r"(a[1]), "r"(a[2]), "r"(a[3]), "r"(b0), "r"(b1));
}
__device__ __forceinline__ void mma_bf16(float* d, const uint32_t* a, uint32_t b0, uint32_t b1) {
    asm volatile("mma.sync.aligned.m16n8k16.row.col.f32.bf16.bf16.f32 "
                 "{%0,%1,%2,%3}, {%4,%5,%6,%7}, {%8,%9}, {%0,%1,%2,%3};"
                 : "+f"(d[0]), "+f"(d[1]), "+f"(d[2]), "+f"(d[3])
                 : "r"(a[0]), "r"(a[1]), "r"(a[2]), "r"(a[3]), "r"(b0), "r"(b1));
}
__device__ __forceinline__ void cp_async16(uint32_t saddr, const void* gaddr) {
    asm volatile("cp.async.ca.shared.global [%0], [%1], 16;" :: "r"(saddr), "l"(gaddr));
}
#define CP_ASYNC_COMMIT() asm volatile("cp.async.commit_group;" ::: "memory")
#define CP_ASYNC_WAIT0()  asm volatile("cp.async.wait_group 0;"  ::: "memory")

__device__ __forceinline__ float tanh_hw(float x) {
    float r;
    asm("tanh.approx.f32 %0, %1;" : "=f"(r) : "f"(x));
    return r;
}

// ===========================================================================
// Scratch
// ===========================================================================
__device__ float g_qproj[Bsz * Hsz];
__device__ float g_x0[Bsz * X0W];
__device__ float g_gi[Bsz * 3 * Hsz];
__device__ float g_gh[Bsz * 3 * Hsz];
__device__ __half g_wkH[Hsz * Dsz];                    // Wk fp16 (fused kernel)
// bf16 hi/lo weight splits (zero-initialized device globals; Wout padded)
__device__ __nv_bfloat16 g_wqH[Hsz * Hsz],       g_wqL[Hsz * Hsz];
__device__ __nv_bfloat16 g_wih0H[384 * X0W],     g_wih0L[384 * X0W];
__device__ __nv_bfloat16 g_whh0H[384 * Hsz],     g_whh0L[384 * Hsz];
__device__ __nv_bfloat16 g_wih1H[384 * Hsz],     g_wih1L[384 * Hsz];
__device__ __nv_bfloat16 g_whh1H[384 * Hsz],     g_whh1L[384 * Hsz];
__device__ __nv_bfloat16 g_woutH[1024 * Hsz],    g_woutL[1024 * Hsz];

// ---------------------------------------------------------------------------
// Prep: split all weights to bf16 hi/lo, Wk to fp16, copy embed into g_x0.
// ---------------------------------------------------------------------------
__device__ __forceinline__ void bf_split(float w, __nv_bfloat16* H, __nv_bfloat16* L, int j) {
    __nv_bfloat16 hi = __float2bfloat16(w);
    H[j] = hi;
    L[j] = __float2bfloat16(w - __bfloat162float(hi));
}

#define O1 16384
#define O2 139264
#define O3 188416
#define O4 237568
#define O5 286720
#define O6 414720
#define O7 447488
#define OT 578560

__global__ void prep_kernel(
    const float* __restrict__ wq,   const float* __restrict__ wih0,
    const float* __restrict__ whh0, const float* __restrict__ wih1,
    const float* __restrict__ whh1, const float* __restrict__ wout,
    const float* __restrict__ wk,   const float* __restrict__ embed)
{
    int i = blockIdx.x * blockDim.x + threadIdx.x;
    if (i >= OT) return;
    if (i < O1)      bf_split(wq[i],        g_wqH,   g_wqL,   i);
    else if (i < O2) { int j = i - O1; bf_split(wih0[j], g_wih0H, g_wih0L, j); }
    else if (i < O3) { int j = i - O2; bf_split(whh0[j], g_whh0H, g_whh0L, j); }
    else if (i < O4) { int j = i - O3; bf_split(wih1[j], g_wih1H, g_wih1L, j); }
    else if (i < O5) { int j = i - O4; bf_split(whh1[j], g_whh1H, g_whh1L, j); }
    else if (i < O6) { int j = i - O5; bf_split(wout[j], g_woutH, g_woutL, j); }
    else if (i < O7) { int j = i - O6; g_wkH[j] = __float2half_rn(wk[j]); }
    else             { int j = i - O7; int b = j >> 6, e = j & 63;
                       g_x0[b * X0W + e] = embed[b * 64 + e]; }
}

// ===========================================================================
// Tensor-core GEMM (3-term bf16 split): C[m,n] = A[m,:K] . W[n,:K] + bias[n]
// CTA tile 128m x 128n, K chunks of 64. 8 warps as 4(m) x 2(n): 32x64 each.
// W provided pre-split (hi/lo bf16, row stride K, rows zero-padded to tile).
// ===========================================================================
#define GB_SA_HI 0
#define GB_SA_LO 16384
#define GB_SB_HI 32768
#define GB_SB_LO 49152
#define GB_SMEM  65536

__global__ __launch_bounds__(256, 2) void mma_gemm_kernel(
    const float* __restrict__ A, int lda, int nChunks,
    const __nv_bfloat16* __restrict__ wH, const __nv_bfloat16* __restrict__ wL,
    const float* __restrict__ bias, float* __restrict__ C, int N)
{
    extern __shared__ char smem[];
    uint32_t sbase = smem_to_u32(smem);
    int t    = threadIdx.x;
    int lane = t & 31, w = t >> 5;
    int wr   = w & 3,  wc = w >> 2;
    int m0   = blockIdx.y * 128;
    int n0   = blockIdx.x * 128;

    float acc[2][8][4];
    #pragma unroll
    for (int mt = 0; mt < 2; mt++)
        #pragma unroll
        for (int nt = 0; nt < 8; nt++)
            #pragma unroll
            for (int i = 0; i < 4; i++) acc[mt][nt][i] = 0.f;

    for (int c = 0; c < nChunks; c++) {
        int d0 = c * 64;
        // ---- W chunk via cp.async (hi/lo), SW128 on 128B rows ----
        #pragma unroll
        for (int i = 0; i < 4; i++) {
            int idx = t + i * 256;          // 16B units, 8 per row
            int row = idx >> 3;
            int u   = idx & 7;
            uint32_t off = SMEM_SWIZZLE_128B((uint32_t)(row * 128 + u * 16));
            const __nv_bfloat16* sh = wH + (size_t)(n0 + row) * lda + d0 + u * 8;
            const __nv_bfloat16* sl = wL + (size_t)(n0 + row) * lda + d0 + u * 8;
            cp_async16(sbase + GB_SB_HI + off, sh);
            cp_async16(sbase + GB_SB_LO + off, sl);
        }
        CP_ASYNC_COMMIT();
        // ---- A chunk: fp32 -> bf16 hi/lo ----
        #pragma unroll
        for (int i = 0; i < 8; i++) {
            int idx = t + i * 256;          // float4 units, 16 per row
            int row = idx >> 4;
            int dq  = idx & 15;
            float4 v4 = *(const float4*)(A + (size_t)(m0 + row) * lda + d0 + dq * 4);
            __nv_bfloat16 h0 = __float2bfloat16(v4.x);
            __nv_bfloat16 h1 = __float2bfloat16(v4.y);
            __nv_bfloat16 h2 = __float2bfloat16(v4.z);
            __nv_bfloat16 h3 = __float2bfloat16(v4.w);
            __nv_bfloat16 r0 = __float2bfloat16(v4.x - __bfloat162float(h0));
            __nv_bfloat16 r1 = __float2bfloat16(v4.y - __bfloat162float(h1));
            __nv_bfloat16 r2 = __float2bfloat16(v4.z - __bfloat162float(h2));
            __nv_bfloat16 r3 = __float2bfloat16(v4.w - __bfloat162float(h3));
            uint32_t off = SMEM_SWIZZLE_128B((uint32_t)(row * 128 + dq * 8));
            uint2 hv, lv;
            hv.x = (uint32_t)__bfloat16_as_ushort(h0) | ((uint32_t)__bfloat16_as_ushort(h1) << 16);
            hv.y = (uint32_t)__bfloat16_as_ushort(h2) | ((uint32_t)__bfloat16_as_ushort(h3) << 16);
            lv.x = (uint32_t)__bfloat16_as_ushort(r0) | ((uint32_t)__bfloat16_as_ushort(r1) << 16);
            lv.y = (uint32_t)__bfloat16_as_ushort(r2) | ((uint32_t)__bfloat16_as_ushort(r3) << 16);
            *(uint2*)(smem + GB_SA_HI + off) = hv;
            *(uint2*)(smem + GB_SA_LO + off) = lv;
        }
        CP_ASYNC_WAIT0();
        __syncthreads();

        #pragma unroll
        for (int ks = 0; ks < 4; ks++) {
            int kb = ks * 32;
            uint32_t ah[2][4], al[2][4];
            #pragma unroll
            for (int mt = 0; mt < 2; mt++) {
                int row  = wr * 32 + mt * 16 + (lane & 15);
                int colb = kb + (lane >> 4) * 16;
                uint32_t off = SMEM_SWIZZLE_128B((uint32_t)(row * 128 + colb));
                ldmat4(ah[mt], sbase + GB_SA_HI + off);
                ldmat4(al[mt], sbase + GB_SA_LO + off);
            }
            #pragma unroll
            for (int p = 0; p < 4; p++) {
                int row  = wc * 64 + p * 16 + (lane & 15);
                int colb = kb + (lane >> 4) * 16;
                uint32_t off = SMEM_SWIZZLE_128B((uint32_t)(row * 128 + colb));
                uint32_t rh[4], rl[4];
                ldmat4(rh, sbase + GB_SB_HI + off);
                ldmat4(rl, sbase + GB_SB_LO + off);
                #pragma unroll
                for (int mt = 0; mt < 2; mt++) {
                    mma_bf16(acc[mt][p*2],   ah[mt], rh[0], rh[2]);
                    mma_bf16(acc[mt][p*2+1], ah[mt], rh[1], rh[3]);
                    mma_bf16(acc[mt][p*2],   al[mt], rh[0], rh[2]);
                    mma_bf16(acc[mt][p*2+1], al[mt], rh[1], rh[3]);
                    mma_bf16(acc[mt][p*2],   ah[mt], rl[0], rl[2]);
                    mma_bf16(acc[mt][p*2+1], ah[mt], rl[1], rl[3]);
                }
            }
        }
        __syncthreads();
    }

    // ---- store ----
    #pragma unroll
    for (int mt = 0; mt < 2; mt++)
        #pragma unroll
        for (int nt = 0; nt < 8; nt++)
            #pragma unroll
            for (int i = 0; i < 4; i++) {
                int row = m0 + wr * 32 + mt * 16 + (lane >> 2) + (i >= 2 ? 8 : 0);
                int col = n0 + wc * 64 + nt * 8 + (lane & 3) * 2 + (i & 1);
                if (col < N) {
                    float v = acc[mt][nt][i];
                    if (bias) v += bias[col];
                    C[(size_t)row * N + col] = v;
                }
            }
}

// ===========================================================================
// FUSED scores + softmax + context (fixed-max). One block per batch row.
// ctx written directly into g_x0 (concat eliminated).
// ===========================================================================
#define SB_OFF 0
#define SA_OFF 65536
#define FS_SMEM (65536 + 32768)

__global__ __launch_bounds__(256, 2) void fused_attn_kernel(
    const float* __restrict__ enc, const float* __restrict__ attn_v,
    float* __restrict__ attnw_out, float* __restrict__ x0_out)
{
    extern __shared__ char smem[];
    __shared__ float qs[128], vs[128];
    __shared__ float sred[4][64];
    __shared__ float e_all[Lsz];
    __shared__ float e_w[64];
    __shared__ float zred[2];
    __shared__ float sm_invZ;

    uint32_t sbase = smem_to_u32(smem);
    int t    = threadIdx.x;
    int lane = t & 31, w = t >> 5;
    int wr   = w & 1,  wc = w >> 1;
    int b    = blockIdx.x;

    #pragma unroll
    for (int i = 0; i < 16; i++) {
        int u   = t + i * 256;
        int row = u >> 5;
        int cu  = u & 31;
        uint32_t dst = sbase + SB_OFF + (uint32_t)(row * 512 + ((cu ^ (row & 7)) << 4));
        cp_async16(dst, g_wkH + (size_t)row * Dsz + cu * 8);
    }
    CP_ASYNC_COMMIT();

    if (t < 128) { qs[t] = g_qproj[b * Hsz + t]; vs[t] = attn_v[t]; }

    const float* encb = enc + (size_t)b * Lsz * Dsz;
    float2 ctx = make_float2(0.f, 0.f);
    float Zloc = 0.f;

    int s_row = t >> 5;
    int s_cu  = t & 31;

    // quarter-tile prefetch (16 regs)
    float4 pf[4];
    #pragma unroll
    for (int i = 0; i < 2; i++) {
        const float* src = encb + (size_t)(s_row + i * 8) * Dsz + s_cu * 8;
        pf[i * 2]     = *(const float4*)(src);
        pf[i * 2 + 1] = *(const float4*)(src + 4);
    }

    for (int tile = 0; tile < 8; tile++) {
        int l0 = tile * 64;
        #pragma unroll
        for (int i = 0; i < 2; i++) {
            int row = s_row + i * 8;
            __half2 h0 = __floats2half2_rn(pf[i*2].x,   pf[i*2].y);
            __half2 h1 = __floats2half2_rn(pf[i*2].z,   pf[i*2].w);
            __half2 h2 = __floats2half2_rn(pf[i*2+1].x, pf[i*2+1].y);
            __half2 h3 = __floats2half2_rn(pf[i*2+1].z, pf[i*2+1].w);
            uint4 pk;
            pk.x = *(uint32_t*)&h0; pk.y = *(uint32_t*)&h1;
            pk.z = *(uint32_t*)&h2; pk.w = *(uint32_t*)&h3;
            uint32_t off = (uint32_t)(row * 512 + ((s_cu ^ (row & 7)) << 4));
            *(uint4*)(smem + SA_OFF + off) = pk;
        }
        #pragma unroll
        for (int i = 2; i < 8; i++) {
            int row = s_row + i * 8;
            const float* src = encb + (size_t)(l0 + row) * Dsz + s_cu * 8;
            float4 v0 = *(const float4*)(src);
            float4 v1 = *(const float4*)(src + 4);
            __half2 h0 = __floats2half2_rn(v0.x, v0.y);
            __half2 h1 = __floats2half2_rn(v0.z, v0.w);
            __half2 h2 = __floats2half2_rn(v1.x, v1.y);
            __half2 h3 = __floats2half2_rn(v1.z, v1.w);
            uint4 pk;
            pk.x = *(uint32_t*)&h0; pk.y = *(uint32_t*)&h1;
            pk.z = *(uint32_t*)&h2; pk.w = *(uint32_t*)&h3;
            uint32_t off = (uint32_t)(row * 512 + ((s_cu ^ (row & 7)) << 4));
            *(uint4*)(smem + SA_OFF + off) = pk;
        }
        if (tile == 0) CP_ASYNC_WAIT0();
        __syncthreads();

        if (tile < 7) {
            const float* nb = encb + (size_t)(l0 + 64) * Dsz;
            #pragma unroll
            for (int i = 0; i < 2; i++) {
                const float* src = nb + (size_t)(s_row + i * 8) * Dsz + s_cu * 8;
                pf[i * 2]     = *(const float4*)(src);
                pf[i * 2 + 1] = *(const float4*)(src + 4);
            }
        }

        float acc[2][4][4];
        #pragma unroll
        for (int mt = 0; mt < 2; mt++)
            #pragma unroll
            for (int nt = 0; nt < 4; nt++)
                #pragma unroll
                for (int i = 0; i < 4; i++) acc[mt][nt][i] = 0.f;

        #pragma unroll
        for (int ks = 0; ks < 16; ks++) {
            int cuk = ks * 2 + (lane >> 4);
            uint32_t ah[2][4];
            #pragma unroll
            for (int mt = 0; mt < 2; mt++) {
                int row = wr * 32 + mt * 16 + (lane & 15);
                uint32_t off = (uint32_t)(row * 512 + ((cuk ^ (row & 7)) << 4));
                ldmat4(ah[mt], sbase + SA_OFF + off);
            }
            #pragma unroll
            for (int p = 0; p < 2; p++) {
                int row = wc * 32 + p * 16 + (lane & 15);
                uint32_t off = (uint32_t)(row * 512 + ((cuk ^ (row & 7)) << 4));
                uint32_t rb[4];
                ldmat4(rb, sbase + SB_OFF + off);
                #pragma unroll
                for (int mt = 0; mt < 2; mt++) {
                    mma_f16(acc[mt][p*2],   ah[mt], rb[0], rb[2]);
                    mma_f16(acc[mt][p*2+1], ah[mt], rb[1], rb[3]);
                }
            }
        }

        float part[4];
        #pragma unroll
        for (int mt = 0; mt < 2; mt++)
            #pragma unroll
            for (int half = 0; half < 2; half++) {
                float p = 0.f;
                #pragma unroll
                for (int nt = 0; nt < 4; nt++)
                    #pragma unroll
                    for (int j = 0; j < 2; j++) {
                        int h = wc * 32 + nt * 8 + (lane & 3) * 2 + j;
                        float e = acc[mt][nt][half * 2 + j] + qs[h];
                        p += vs[h] * tanh_hw(e);
                    }
                part[mt * 2 + half] = p;
            }
        #pragma unroll
        for (int k = 0; k < 4; k++) {
            part[k] += __shfl_xor_sync(0xffffffffu, part[k], 1);
            part[k] += __shfl_xor_sync(0xffffffffu, part[k], 2);
        }
        if ((lane & 3) == 0) {
            #pragma unroll
            for (int mt = 0; mt < 2; mt++)
                #pragma unroll
                for (int half = 0; half < 2; half++) {
                    int row = wr * 32 + mt * 16 + half * 8 + (lane >> 2);
                    sred[wc][row] = part[mt * 2 + half];
                }
        }
        __syncthreads();

        if (t < 64) {
            float s = sred[0][t] + sred[1][t] + sred[2][t] + sred[3][t];
            float e = __expf(s);
            e_w[t] = e;
            e_all[l0 + t] = e;
            Zloc += e;
        }
        __syncthreads();

        if (t < 128) {
            int cu = t >> 2, byo = (4 * t) & 15;
            float2 cacc = make_float2(0.f, 0.f);
            #pragma unroll 8
            for (int l = 0; l < 64; l++) {
                uint32_t off = (uint32_t)(l * 512 + ((cu ^ (l & 7)) << 4) + byo);
                __half2 hv = *(const __half2*)(smem + SA_OFF + off);
                float2 fv = __half22float2(hv);
                float e = e_w[l];
                cacc.x += e * fv.x;
                cacc.y += e * fv.y;
            }
            ctx.x += cacc.x;
            ctx.y += cacc.y;
        }
        __syncthreads();
    }

    if (t < 64) {
        float z = Zloc;
        #pragma unroll
        for (int o = 16; o > 0; o >>= 1)
            z += __shfl_xor_sync(0xffffffffu, z, o);
        if (lane == 0) zred[t >> 5] = z;
    }
    __syncthreads();
    if (t == 0) sm_invZ = 1.f / (zred[0] + zred[1]);
    __syncthreads();

    float invZ = sm_invZ;
    if (t < 128) {
        // ctx directly into x0 (columns E..E+D)
        x0_out[(size_t)b * X0W + Esz + 2 * t]     = ctx.x * invZ;
        x0_out[(size_t)b * X0W + Esz + 2 * t + 1] = ctx.y * invZ;
    }
    attnw_out[(size_t)b * Lsz + t]       = e_all[t]       * invZ;
    attnw_out[(size_t)b * Lsz + t + 256] = e_all[t + 256] * invZ;
}

// ---------------------------------------------------------------------------
__global__ void gru_kernel(const float* __restrict__ hprev, float* __restrict__ hnew) {
    int b = blockIdx.x, h = threadIdx.x;
    int base = b * 3 * Hsz;
    float r = 1.f / (1.f + __expf(-(g_gi[base + h]       + g_gh[base + h])));
    float z = 1.f / (1.f + __expf(-(g_gi[base + Hsz + h] + g_gh[base + Hsz + h])));
    float n = tanhf(g_gi[base + 2 * Hsz + h] + r * g_gh[base + 2 * Hsz + h]);
    hnew[b * Hsz + h] = (1.f - z) * n + z * hprev[b * Hsz + h];
}

// ===========================================================================
extern "C" void kernel_launch(void* const* d_in, const int* in_sizes, int n_in,
                              void* d_out, int out_size)
{
    const float* embed  = (const float*)d_in[0];
    const float* hidden = (const float*)d_in[1];
    const float* enc    = (const float*)d_in[2];
    const float* Wq     = (const float*)d_in[3];
    const float* Wk     = (const float*)d_in[4];
    const float* av     = (const float*)d_in[5];
    const float* Wih0   = (const float*)d_in[6];
    const float* Whh0   = (const float*)d_in[7];
    const float* bih0   = (const float*)d_in[8];
    const float* bhh0   = (const float*)d_in[9];
    const float* Wih1   = (const float*)d_in[10];
    const float* Whh1   = (const float*)d_in[11];
    const float* bih1   = (const float*)d_in[12];
    const float* bhh1   = (const float*)d_in[13];
    const float* Wout   = (const float*)d_in[14];
    const float* bout   = (const float*)d_in[15];

    float* out_logits = (float*)d_out;
    float* out_hidden = out_logits + (size_t)Bsz * Vsz;
    float* out_attnw  = out_hidden + (size_t)2 * Bsz * Hsz;

    float *p_qproj, *p_x0, *p_gi, *p_gh;
    cudaGetSymbolAddress((void**)&p_qproj, g_qproj);
    cudaGetSymbolAddress((void**)&p_x0,    g_x0);
    cudaGetSymbolAddress((void**)&p_gi,    g_gi);
    cudaGetSymbolAddress((void**)&p_gh,    g_gh);

    __nv_bfloat16 *wqH, *wqL, *wih0H, *wih0L, *whh0H, *whh0L,
                  *wih1H, *wih1L, *whh1H, *whh1L, *woutH, *woutL;
    cudaGetSymbolAddress((void**)&wqH,   g_wqH);   cudaGetSymbolAddress((void**)&wqL,   g_wqL);
    cudaGetSymbolAddress((void**)&wih0H, g_wih0H); cudaGetSymbolAddress((void**)&wih0L, g_wih0L);
    cudaGetSymbolAddress((void**)&whh0H, g_whh0H); cudaGetSymbolAddress((void**)&whh0L, g_whh0L);
    cudaGetSymbolAddress((void**)&wih1H, g_wih1H); cudaGetSymbolAddress((void**)&wih1L, g_wih1L);
    cudaGetSymbolAddress((void**)&whh1H, g_whh1H); cudaGetSymbolAddress((void**)&whh1L, g_whh1L);
    cudaGetSymbolAddress((void**)&woutH, g_woutH); cudaGetSymbolAddress((void**)&woutL, g_woutL);

    cudaFuncSetAttribute(fused_attn_kernel,
                         cudaFuncAttributeMaxDynamicSharedMemorySize, FS_SMEM);
    cudaFuncSetAttribute(mma_gemm_kernel,
                         cudaFuncAttributeMaxDynamicSharedMemorySize, GB_SMEM);

    const float* h0_prev = hidden;
    const float* h1_prev = hidden + (size_t)Bsz * Hsz;

    // 1) prep: weight splits + Wk fp16 + embed copy into x0
    prep_kernel<<<(OT + 255) / 256, 256>>>(Wq, Wih0, Whh0, Wih1, Whh1, Wout, Wk, embed);

    // 2) qproj = h1 @ Wq^T
    mma_gemm_kernel<<<dim3(1, 16), 256, GB_SMEM>>>(
        h1_prev, Hsz, 2, wqH, wqL, nullptr, p_qproj, Hsz);

    // 3) fused attention (scores + softmax + ctx -> x0)
    fused_attn_kernel<<<Bsz, 256, FS_SMEM>>>(enc, av, out_attnw, p_x0);

    // 4) GRU layer 0
    mma_gemm_kernel<<<dim3(3, 16), 256, GB_SMEM>>>(
        p_x0, X0W, 5, wih0H, wih0L, bih0, p_gi, 384);
    mma_gemm_kernel<<<dim3(3, 16), 256, GB_SMEM>>>(
        h0_prev, Hsz, 2, whh0H, whh0L, bhh0, p_gh, 384);
    gru_kernel<<<Bsz, Hsz>>>(h0_prev, out_hidden);

    // 5) GRU layer 1
    mma_gemm_kernel<<<dim3(3, 16), 256, GB_SMEM>>>(
        out_hidden, Hsz, 2, wih1H, wih1L, bih1, p_gi, 384);
    mma_gemm_kernel<<<dim3(3, 16), 256, GB_SMEM>>>(
        h1_prev, Hsz, 2, whh1H, whh1L, bhh1, p_gh, 384);
    gru_kernel<<<Bsz, Hsz>>>(h1_prev, out_hidden + (size_t)Bsz * Hsz);

    // 6) logits = h1new @ Wout^T + bout  (Wout zero-padded to 1024 rows)
    mma_gemm_kernel<<<dim3(8, 16), 256, GB_SMEM>>>(
        out_hidden + (size_t)Bsz * Hsz, Hsz, 2, woutH, woutL, bout, out_logits, Vsz);
}

// round 13
// speedup vs baseline: 3.6921x; 1.0281x over previous
#include <cuda_runtime.h>
#include <cuda_bf16.h>
#include <cuda_fp16.h>
#include <cstdint>

#define Bsz 2048
#define Lsz 512
#define Esz 64
#define Hsz 128
#define Dsz 256
#define Vsz 1000
#define X0W 320                      // E + D

#define SMEM_SWIZZLE_128B(off) ((off) ^ (((off) >> 3) & 0x70))

__device__ __forceinline__ uint32_t smem_to_u32(const void* p) {
    uint32_t a;
    asm("{ .reg .u64 t; cvta.to.shared.u64 t, %1; cvt.u32.u64 %0, t; }"
        : "=r"(a) : "l"(p));
    return a;
}
__device__ __forceinline__ void ldmat4(uint32_t* r, uint32_t addr) {
    asm volatile("ldmatrix.sync.aligned.m8n8.x4.shared.b16 {%0,%1,%2,%3}, [%4];"
                 : "=r"(r[0]), "=r"(r[1]), "=r"(r[2]), "=r"(r[3]) : "r"(addr));
}
__device__ __forceinline__ void mma_f16(float* d, const uint32_t* a, uint32_t b0, uint32_t b1) {
    asm volatile("mma.sync.aligned.m16n8k16.row.col.f32.f16.f16.f32 "
                 "{%0,%1,%2,%3}, {%4,%5,%6,%7}, {%8,%9}, {%0,%1,%2,%3};"
                 : "+f"(d[0]), "+f"(d[1]), "+f"(d[2]), "+f"(d[3])
                 : "r"(a[0]), "r"(a[1]), "r"(a[2]), "r"(a[3]), "r"(b0), "r"(b1));
}
__device__ __forceinline__ void mma_bf16(float* d, const uint32_t* a, uint32_t b0, uint32_t b1) {
    asm volatile("mma.sync.aligned.m16n8k16.row.col.f32.bf16.bf16.f32 "
                 "{%0,%1,%2,%3}, {%4,%5,%6,%7}, {%8,%9}, {%0,%1,%2,%3};"
                 : "+f"(d[0]), "+f"(d[1]), "+f"(d[2]), "+f"(d[3])
                 : "r"(a[0]), "r"(a[1]), "r"(a[2]), "r"(a[3]), "r"(b0), "r"(b1));
}
__device__ __forceinline__ void cp_async16(uint32_t saddr, const void* gaddr) {
    asm volatile("cp.async.ca.shared.global [%0], [%1], 16;" :: "r"(saddr), "l"(gaddr));
}
#define CP_ASYNC_COMMIT() asm volatile("cp.async.commit_group;" ::: "memory")
#define CP_ASYNC_WAIT0()  asm volatile("cp.async.wait_group 0;"  ::: "memory")

__device__ __forceinline__ float tanh_hw(float x) {
    float r;
    asm("tanh.approx.f32 %0, %1;" : "=f"(r) : "f"(x));
    return r;
}

// ===========================================================================
// Scratch
// ===========================================================================
__device__ float g_qproj[Bsz * Hsz];
__device__ float g_x0[Bsz * X0W];
__device__ float g_gi[Bsz * 3 * Hsz];
__device__ float g_gh[Bsz * 3 * Hsz];
__device__ __half g_wkH[Hsz * Dsz];
__device__ __nv_bfloat16 g_wqH[Hsz * Hsz],       g_wqL[Hsz * Hsz];
__device__ __nv_bfloat16 g_wih0H[384 * X0W],     g_wih0L[384 * X0W];
__device__ __nv_bfloat16 g_whh0H[384 * Hsz],     g_whh0L[384 * Hsz];
__device__ __nv_bfloat16 g_wih1H[384 * Hsz],     g_wih1L[384 * Hsz];
__device__ __nv_bfloat16 g_whh1H[384 * Hsz],     g_whh1L[384 * Hsz];
__device__ __nv_bfloat16 g_woutH[1024 * Hsz],    g_woutL[1024 * Hsz];

// ---------------------------------------------------------------------------
__device__ __forceinline__ void bf_split(float w, __nv_bfloat16* H, __nv_bfloat16* L, int j) {
    __nv_bfloat16 hi = __float2bfloat16(w);
    H[j] = hi;
    L[j] = __float2bfloat16(w - __bfloat162float(hi));
}

#define O1 16384
#define O2 139264
#define O3 188416
#define O4 237568
#define O5 286720
#define O6 414720
#define O7 447488
#define OT 578560

__global__ void prep_kernel(
    const float* __restrict__ wq,   const float* __restrict__ wih0,
    const float* __restrict__ whh0, const float* __restrict__ wih1,
    const float* __restrict__ whh1, const float* __restrict__ wout,
    const float* __restrict__ wk,   const float* __restrict__ embed)
{
    int i = blockIdx.x * blockDim.x + threadIdx.x;
    if (i >= OT) return;
    if (i < O1)      bf_split(wq[i],        g_wqH,   g_wqL,   i);
    else if (i < O2) { int j = i - O1; bf_split(wih0[j], g_wih0H, g_wih0L, j); }
    else if (i < O3) { int j = i - O2; bf_split(whh0[j], g_whh0H, g_whh0L, j); }
    else if (i < O4) { int j = i - O3; bf_split(wih1[j], g_wih1H, g_wih1L, j); }
    else if (i < O5) { int j = i - O4; bf_split(whh1[j], g_whh1H, g_whh1L, j); }
    else if (i < O6) { int j = i - O5; bf_split(wout[j], g_woutH, g_woutL, j); }
    else if (i < O7) { int j = i - O6; g_wkH[j] = __float2half_rn(wk[j]); }
    else             { int j = i - O7; int b = j >> 6, e = j & 63;
                       g_x0[b * X0W + e] = embed[b * 64 + e]; }
}

// ===========================================================================
// Tensor-core GEMM (3-term bf16 split) — unchanged from R10
// ===========================================================================
#define GB_SA_HI 0
#define GB_SA_LO 16384
#define GB_SB_HI 32768
#define GB_SB_LO 49152
#define GB_SMEM  65536

__global__ __launch_bounds__(256, 2) void mma_gemm_kernel(
    const float* __restrict__ A, int lda, int nChunks,
    const __nv_bfloat16* __restrict__ wH, const __nv_bfloat16* __restrict__ wL,
    const float* __restrict__ bias, float* __restrict__ C, int N)
{
    extern __shared__ char smem[];
    uint32_t sbase = smem_to_u32(smem);
    int t    = threadIdx.x;
    int lane = t & 31, w = t >> 5;
    int wr   = w & 3,  wc = w >> 2;
    int m0   = blockIdx.y * 128;
    int n0   = blockIdx.x * 128;

    float acc[2][8][4];
    #pragma unroll
    for (int mt = 0; mt < 2; mt++)
        #pragma unroll
        for (int nt = 0; nt < 8; nt++)
            #pragma unroll
            for (int i = 0; i < 4; i++) acc[mt][nt][i] = 0.f;

    for (int c = 0; c < nChunks; c++) {
        int d0 = c * 64;
        #pragma unroll
        for (int i = 0; i < 4; i++) {
            int idx = t + i * 256;
            int row = idx >> 3;
            int u   = idx & 7;
            uint32_t off = SMEM_SWIZZLE_128B((uint32_t)(row * 128 + u * 16));
            cp_async16(sbase + GB_SB_HI + off, wH + (size_t)(n0 + row) * lda + d0 + u * 8);
            cp_async16(sbase + GB_SB_LO + off, wL + (size_t)(n0 + row) * lda + d0 + u * 8);
        }
        CP_ASYNC_COMMIT();
        #pragma unroll
        for (int i = 0; i < 8; i++) {
            int idx = t + i * 256;
            int row = idx >> 4;
            int dq  = idx & 15;
            float4 v4 = *(const float4*)(A + (size_t)(m0 + row) * lda + d0 + dq * 4);
            __nv_bfloat16 h0 = __float2bfloat16(v4.x);
            __nv_bfloat16 h1 = __float2bfloat16(v4.y);
            __nv_bfloat16 h2 = __float2bfloat16(v4.z);
            __nv_bfloat16 h3 = __float2bfloat16(v4.w);
            __nv_bfloat16 r0 = __float2bfloat16(v4.x - __bfloat162float(h0));
            __nv_bfloat16 r1 = __float2bfloat16(v4.y - __bfloat162float(h1));
            __nv_bfloat16 r2 = __float2bfloat16(v4.z - __bfloat162float(h2));
            __nv_bfloat16 r3 = __float2bfloat16(v4.w - __bfloat162float(h3));
            uint32_t off = SMEM_SWIZZLE_128B((uint32_t)(row * 128 + dq * 8));
            uint2 hv, lv;
            hv.x = (uint32_t)__bfloat16_as_ushort(h0) | ((uint32_t)__bfloat16_as_ushort(h1) << 16);
            hv.y = (uint32_t)__bfloat16_as_ushort(h2) | ((uint32_t)__bfloat16_as_ushort(h3) << 16);
            lv.x = (uint32_t)__bfloat16_as_ushort(r0) | ((uint32_t)__bfloat16_as_ushort(r1) << 16);
            lv.y = (uint32_t)__bfloat16_as_ushort(r2) | ((uint32_t)__bfloat16_as_ushort(r3) << 16);
            *(uint2*)(smem + GB_SA_HI + off) = hv;
            *(uint2*)(smem + GB_SA_LO + off) = lv;
        }
        CP_ASYNC_WAIT0();
        __syncthreads();

        #pragma unroll
        for (int ks = 0; ks < 4; ks++) {
            int kb = ks * 32;
            uint32_t ah[2][4], al[2][4];
            #pragma unroll
            for (int mt = 0; mt < 2; mt++) {
                int row  = wr * 32 + mt * 16 + (lane & 15);
                int colb = kb + (lane >> 4) * 16;
                uint32_t off = SMEM_SWIZZLE_128B((uint32_t)(row * 128 + colb));
                ldmat4(ah[mt], sbase + GB_SA_HI + off);
                ldmat4(al[mt], sbase + GB_SA_LO + off);
            }
            #pragma unroll
            for (int p = 0; p < 4; p++) {
                int row  = wc * 64 + p * 16 + (lane & 15);
                int colb = kb + (lane >> 4) * 16;
                uint32_t off = SMEM_SWIZZLE_128B((uint32_t)(row * 128 + colb));
                uint32_t rh[4], rl[4];
                ldmat4(rh, sbase + GB_SB_HI + off);
                ldmat4(rl, sbase + GB_SB_LO + off);
                #pragma unroll
                for (int mt = 0; mt < 2; mt++) {
                    mma_bf16(acc[mt][p*2],   ah[mt], rh[0], rh[2]);
                    mma_bf16(acc[mt][p*2+1], ah[mt], rh[1], rh[3]);
                    mma_bf16(acc[mt][p*2],   al[mt], rh[0], rh[2]);
                    mma_bf16(acc[mt][p*2+1], al[mt], rh[1], rh[3]);
                    mma_bf16(acc[mt][p*2],   ah[mt], rl[0], rl[2]);
                    mma_bf16(acc[mt][p*2+1], ah[mt], rl[1], rl[3]);
                }
            }
        }
        __syncthreads();
    }

    #pragma unroll
    for (int mt = 0; mt < 2; mt++)
        #pragma unroll
        for (int nt = 0; nt < 8; nt++)
            #pragma unroll
            for (int i = 0; i < 4; i++) {
                int row = m0 + wr * 32 + mt * 16 + (lane >> 2) + (i >= 2 ? 8 : 0);
                int col = n0 + wc * 64 + nt * 8 + (lane & 3) * 2 + (i & 1);
                if (col < N) {
                    float v = acc[mt][nt][i];
                    if (bias) v += bias[col];
                    C[(size_t)row * N + col] = v;
                }
            }
}

// ===========================================================================
// FUSED attention, software-pipelined: 16 tiles of 32 l-rows, double-buffered
// SA, full next-tile LDG prefetch issued before MMA. 8 warps x 16 h-cols.
// ===========================================================================
#define SB_OFF 0                 // Wk fp16 resident: 64KB
#define SA_OFF 65536             // 2 buffers x (32 rows x 512B) = 32KB
#define FS_SMEM (65536 + 32768)

__global__ __launch_bounds__(256, 2) void fused_attn_kernel(
    const float* __restrict__ enc, const float* __restrict__ attn_v,
    float* __restrict__ attnw_out, float* __restrict__ x0_out)
{
    extern __shared__ char smem[];
    __shared__ float qs[128], vs[128];
    __shared__ float sred[8][32];
    __shared__ float e_all[Lsz];
    __shared__ float e_w[32];
    __shared__ float sm_invZ;

    uint32_t sbase = smem_to_u32(smem);
    int t    = threadIdx.x;
    int lane = t & 31, w = t >> 5;
    int b    = blockIdx.x;

    // ---- preload Wk fp16 (64KB) ----
    #pragma unroll
    for (int i = 0; i < 16; i++) {
        int u   = t + i * 256;
        int row = u >> 5;
        int cu  = u & 31;
        uint32_t dst = sbase + SB_OFF + (uint32_t)(row * 512 + ((cu ^ (row & 7)) << 4));
        cp_async16(dst, g_wkH + (size_t)row * Dsz + cu * 8);
    }
    CP_ASYNC_COMMIT();

    if (t < 128) { qs[t] = g_qproj[b * Hsz + t]; vs[t] = attn_v[t]; }

    const float* encb = enc + (size_t)b * Lsz * Dsz;
    float2 ctx = make_float2(0.f, 0.f);   // t<128 owns d = 2t, 2t+1
    float Zloc = 0.f;                      // t<32 partial

    int s_row = t >> 5;                    // 0..7; unit rows = s_row + i*8
    int s_cu  = t & 31;

    // ---- full prefetch of tile 0 (4 units x 2 float4 = 32 regs) ----
    float4 pf[8];
    #pragma unroll
    for (int i = 0; i < 4; i++) {
        const float* src = encb + (size_t)(s_row + i * 8) * Dsz + s_cu * 8;
        pf[i * 2]     = *(const float4*)(src);
        pf[i * 2 + 1] = *(const float4*)(src + 4);
    }

    for (int tile = 0; tile < 16; tile++) {
        uint32_t bufo = SA_OFF + (uint32_t)((tile & 1) << 14);   // 16KB buffers
        // ---- stage tile from regs ----
        #pragma unroll
        for (int i = 0; i < 4; i++) {
            int row = s_row + i * 8;
            __half2 h0 = __floats2half2_rn(pf[i*2].x,   pf[i*2].y);
            __half2 h1 = __floats2half2_rn(pf[i*2].z,   pf[i*2].w);
            __half2 h2 = __floats2half2_rn(pf[i*2+1].x, pf[i*2+1].y);
            __half2 h3 = __floats2half2_rn(pf[i*2+1].z, pf[i*2+1].w);
            uint4 pk;
            pk.x = *(uint32_t*)&h0; pk.y = *(uint32_t*)&h1;
            pk.z = *(uint32_t*)&h2; pk.w = *(uint32_t*)&h3;
            uint32_t off = (uint32_t)(row * 512 + ((s_cu ^ (row & 7)) << 4));
            *(uint4*)(smem + bufo + off) = pk;
        }
        if (tile == 0) CP_ASYNC_WAIT0();
        __syncthreads();                                    // S1: tile visible

        // ---- issue LDGs for next tile (hidden behind MMA+epi+ctx) ----
        if (tile < 15) {
            const float* nb = encb + (size_t)((tile + 1) * 32) * Dsz;
            #pragma unroll
            for (int i = 0; i < 4; i++) {
                const float* src = nb + (size_t)(s_row + i * 8) * Dsz + s_cu * 8;
                pf[i * 2]     = *(const float4*)(src);
                pf[i * 2 + 1] = *(const float4*)(src + 4);
            }
        }

        // ---- MMA: 32l x 128h, K=256; warp w owns h-cols [16w, 16w+16) ----
        float acc[2][2][4];
        #pragma unroll
        for (int mt = 0; mt < 2; mt++)
            #pragma unroll
            for (int nt = 0; nt < 2; nt++)
                #pragma unroll
                for (int i = 0; i < 4; i++) acc[mt][nt][i] = 0.f;

        #pragma unroll
        for (int ks = 0; ks < 16; ks++) {
            int cuk = ks * 2 + (lane >> 4);
            uint32_t ah[2][4];
            #pragma unroll
            for (int mt = 0; mt < 2; mt++) {
                int row = mt * 16 + (lane & 15);
                uint32_t off = (uint32_t)(row * 512 + ((cuk ^ (row & 7)) << 4));
                ldmat4(ah[mt], sbase + bufo + off);
            }
            int brow = w * 16 + (lane & 15);
            uint32_t boff = (uint32_t)(brow * 512 + ((cuk ^ (brow & 7)) << 4));
            uint32_t rb[4];
            ldmat4(rb, sbase + SB_OFF + boff);
            #pragma unroll
            for (int mt = 0; mt < 2; mt++) {
                mma_f16(acc[mt][0], ah[mt], rb[0], rb[2]);
                mma_f16(acc[mt][1], ah[mt], rb[1], rb[3]);
            }
        }

        // ---- epilogue: warp-partial score over its 16 h ----
        float part[4];
        #pragma unroll
        for (int mt = 0; mt < 2; mt++)
            #pragma unroll
            for (int half = 0; half < 2; half++) {
                float p = 0.f;
                #pragma unroll
                for (int nt = 0; nt < 2; nt++)
                    #pragma unroll
                    for (int j = 0; j < 2; j++) {
                        int h = w * 16 + nt * 8 + (lane & 3) * 2 + j;
                        float e = acc[mt][nt][half * 2 + j] + qs[h];
                        p += vs[h] * tanh_hw(e);
                    }
                part[mt * 2 + half] = p;
            }
        #pragma unroll
        for (int k = 0; k < 4; k++) {
            part[k] += __shfl_xor_sync(0xffffffffu, part[k], 1);
            part[k] += __shfl_xor_sync(0xffffffffu, part[k], 2);
        }
        if ((lane & 3) == 0) {
            #pragma unroll
            for (int mt = 0; mt < 2; mt++)
                #pragma unroll
                for (int half = 0; half < 2; half++) {
                    int row = mt * 16 + half * 8 + (lane >> 2);
                    sred[w][row] = part[mt * 2 + half];
                }
        }
        __syncthreads();                                    // S2: sred ready

        // ---- fixed-max softmax partial ----
        if (t < 32) {
            float s = sred[0][t] + sred[1][t] + sred[2][t] + sred[3][t]
                    + sred[4][t] + sred[5][t] + sred[6][t] + sred[7][t];
            float e = __expf(s);
            e_w[t] = e;
            e_all[tile * 32 + t] = e;
            Zloc += e;
        }
        __syncthreads();                                    // S3: e_w ready

        // ---- ctx accumulate from resident fp16 tile ----
        if (t < 128) {
            int cu = t >> 2, byo = (4 * t) & 15;
            float2 cacc = make_float2(0.f, 0.f);
            #pragma unroll 8
            for (int l = 0; l < 32; l++) {
                uint32_t off = (uint32_t)(l * 512 + ((cu ^ (l & 7)) << 4) + byo);
                __half2 hv = *(const __half2*)(smem + bufo + off);
                float2 fv = __half22float2(hv);
                float e = e_w[l];
                cacc.x += e * fv.x;
                cacc.y += e * fv.y;
            }
            ctx.x += cacc.x;
            ctx.y += cacc.y;
        }
        // no sync needed here: next stage writes the OTHER buffer, and
        // S1 of the next iteration orders everything before MMA reads.
    }

    __syncthreads();
    if (t < 32) {
        float z = Zloc;
        #pragma unroll
        for (int o = 16; o > 0; o >>= 1)
            z += __shfl_xor_sync(0xffffffffu, z, o);
        if (lane == 0) sm_invZ = 1.f / z;
    }
    __syncthreads();

    float invZ = sm_invZ;
    if (t < 128) {
        x0_out[(size_t)b * X0W + Esz + 2 * t]     = ctx.x * invZ;
        x0_out[(size_t)b * X0W + Esz + 2 * t + 1] = ctx.y * invZ;
    }
    attnw_out[(size_t)b * Lsz + t]       = e_all[t]       * invZ;
    attnw_out[(size_t)b * Lsz + t + 256] = e_all[t + 256] * invZ;
}

// ---------------------------------------------------------------------------
__global__ void gru_kernel(const float* __restrict__ hprev, float* __restrict__ hnew) {
    int b = blockIdx.x, h = threadIdx.x;
    int base = b * 3 * Hsz;
    float r = 1.f / (1.f + __expf(-(g_gi[base + h]       + g_gh[base + h])));
    float z = 1.f / (1.f + __expf(-(g_gi[base + Hsz + h] + g_gh[base + Hsz + h])));
    float n = tanhf(g_gi[base + 2 * Hsz + h] + r * g_gh[base + 2 * Hsz + h]);
    hnew[b * Hsz + h] = (1.f - z) * n + z * hprev[b * Hsz + h];
}

// ===========================================================================
extern "C" void kernel_launch(void* const* d_in, const int* in_sizes, int n_in,
                              void* d_out, int out_size)
{
    const float* embed  = (const float*)d_in[0];
    const float* hidden = (const float*)d_in[1];
    const float* enc    = (const float*)d_in[2];
    const float* Wq     = (const float*)d_in[3];
    const float* Wk     = (const float*)d_in[4];
    const float* av     = (const float*)d_in[5];
    const float* Wih0   = (const float*)d_in[6];
    const float* Whh0   = (const float*)d_in[7];
    const float* bih0   = (const float*)d_in[8];
    const float* bhh0   = (const float*)d_in[9];
    const float* Wih1   = (const float*)d_in[10];
    const float* Whh1   = (const float*)d_in[11];
    const float* bih1   = (const float*)d_in[12];
    const float* bhh1   = (const float*)d_in[13];
    const float* Wout   = (const float*)d_in[14];
    const float* bout   = (const float*)d_in[15];

    float* out_logits = (float*)d_out;
    float* out_hidden = out_logits + (size_t)Bsz * Vsz;
    float* out_attnw  = out_hidden + (size_t)2 * Bsz * Hsz;

    float *p_qproj, *p_x0, *p_gi, *p_gh;
    cudaGetSymbolAddress((void**)&p_qproj, g_qproj);
    cudaGetSymbolAddress((void**)&p_x0,    g_x0);
    cudaGetSymbolAddress((void**)&p_gi,    g_gi);
    cudaGetSymbolAddress((void**)&p_gh,    g_gh);

    __nv_bfloat16 *wqH, *wqL, *wih0H, *wih0L, *whh0H, *whh0L,
                  *wih1H, *wih1L, *whh1H, *whh1L, *woutH, *woutL;
    cudaGetSymbolAddress((void**)&wqH,   g_wqH);   cudaGetSymbolAddress((void**)&wqL,   g_wqL);
    cudaGetSymbolAddress((void**)&wih0H, g_wih0H); cudaGetSymbolAddress((void**)&wih0L, g_wih0L);
    cudaGetSymbolAddress((void**)&whh0H, g_whh0H); cudaGetSymbolAddress((void**)&whh0L, g_whh0L);
    cudaGetSymbolAddress((void**)&wih1H, g_wih1H); cudaGetSymbolAddress((void**)&wih1L, g_wih1L);
    cudaGetSymbolAddress((void**)&whh1H, g_whh1H); cudaGetSymbolAddress((void**)&whh1L, g_whh1L);
    cudaGetSymbolAddress((void**)&woutH, g_woutH); cudaGetSymbolAddress((void**)&woutL, g_woutL);

    cudaFuncSetAttribute(fused_attn_kernel,
                         cudaFuncAttributeMaxDynamicSharedMemorySize, FS_SMEM);
    cudaFuncSetAttribute(mma_gemm_kernel,
                         cudaFuncAttributeMaxDynamicSharedMemorySize, GB_SMEM);

    const float* h0_prev = hidden;
    const float* h1_prev = hidden + (size_t)Bsz * Hsz;

    // 1) prep
    prep_kernel<<<(OT + 255) / 256, 256>>>(Wq, Wih0, Whh0, Wih1, Whh1, Wout, Wk, embed);

    // 2) qproj
    mma_gemm_kernel<<<dim3(1, 16), 256, GB_SMEM>>>(
        h1_prev, Hsz, 2, wqH, wqL, nullptr, p_qproj, Hsz);

    // 3) fused attention (pipelined)
    fused_attn_kernel<<<Bsz, 256, FS_SMEM>>>(enc, av, out_attnw, p_x0);

    // 4) GRU layer 0
    mma_gemm_kernel<<<dim3(3, 16), 256, GB_SMEM>>>(
        p_x0, X0W, 5, wih0H, wih0L, bih0, p_gi, 384);
    mma_gemm_kernel<<<dim3(3, 16), 256, GB_SMEM>>>(
        h0_prev, Hsz, 2, whh0H, whh0L, bhh0, p_gh, 384);
    gru_kernel<<<Bsz, Hsz>>>(h0_prev, out_hidden);

    // 5) GRU layer 1
    mma_gemm_kernel<<<dim3(3, 16), 256, GB_SMEM>>>(
        out_hidden, Hsz, 2, wih1H, wih1L, bih1, p_gi, 384);
    mma_gemm_kernel<<<dim3(3, 16), 256, GB_SMEM>>>(
        h1_prev, Hsz, 2, whh1H, whh1L, bhh1, p_gh, 384);
    gru_kernel<<<Bsz, Hsz>>>(h1_prev, out_hidden + (size_t)Bsz * Hsz);

    // 6) logits
    mma_gemm_kernel<<<dim3(8, 16), 256, GB_SMEM>>>(
        out_hidden + (size_t)Bsz * Hsz, Hsz, 2, woutH, woutL, bout, out_logits, Vsz);
}